// round 14
// baseline (speedup 1.0000x reference)
#include <cuda_runtime.h>
#include <cuda_fp16.h>
#include <cstdint>

// Problem constants
#define Bk   32
#define Nk   1025
#define Dk   768
#define Hh   12
#define dh   64
#define Tt   256
#define Kc   257
#define NKp  (Nk*Kc)
#define MQ   (Bk*Nk)      // 32800
#define MKV  (Bk*Kc)      // 8224

// Scratch (device globals) — fp16 packed operands (uint32 = 2 consecutive elems)
__device__ float    g_bias[(size_t)Hh*NKp];
__device__ uint32_t g_xh  [MQ*Dk/2];
__device__ uint32_t g_ch  [MKV*Dk/2];     // pooled context, fp16 packed
__device__ uint32_t g_q16 [MQ*Dk/2];      // Q projection, fp16 packed
__device__ uint32_t g_kv16[MKV*Dk];       // KV projection, fp16 packed
__device__ uint32_t g_oh  [MQ*Dk/2];      // attention output, fp16 packed
__device__ uint32_t g_wqh [Dk*Dk/2];
__device__ uint32_t g_wkvh[Dk*Dk];
__device__ uint32_t g_woh [Dk*Dk/2];

// ---------------------------------------------------------------------------
// helpers
// ---------------------------------------------------------------------------
__device__ __forceinline__ uint32_t h2u(float f0, float f1) {
    __half2 h = __floats2half2_rn(f0, f1);
    return *reinterpret_cast<uint32_t*>(&h);
}
__device__ __forceinline__ void mma16h(float* d, const uint32_t* a, uint32_t b0, uint32_t b1) {
    asm volatile(
        "mma.sync.aligned.m16n8k16.row.col.f32.f16.f16.f32 "
        "{%0,%1,%2,%3}, {%4,%5,%6,%7}, {%8,%9}, {%0,%1,%2,%3};"
        : "+f"(d[0]), "+f"(d[1]), "+f"(d[2]), "+f"(d[3])
        : "r"(a[0]), "r"(a[1]), "r"(a[2]), "r"(a[3]), "r"(b0), "r"(b1));
}
__device__ __forceinline__ void ldsm4(uint32_t* d, uint32_t addr) {
    asm volatile("ldmatrix.sync.aligned.m8n8.x4.shared.b16 {%0,%1,%2,%3}, [%4];"
        : "=r"(d[0]), "=r"(d[1]), "=r"(d[2]), "=r"(d[3]) : "r"(addr));
}
__device__ __forceinline__ uint32_t s2u(const void* p) {
    uint32_t a;
    asm("{ .reg .u64 t; cvta.to.shared.u64 t, %1; cvt.u32.u64 %0, t; }" : "=r"(a) : "l"(p));
    return a;
}
#define CP16(dst, src, sz) \
    asm volatile("cp.async.cg.shared.global [%0], [%1], 16, %2;" \
                 :: "r"(dst), "l"(src), "r"(sz) : "memory")
#define CP_COMMIT() asm volatile("cp.async.commit_group;" ::: "memory")
#define CP_WAIT1()  asm volatile("cp.async.wait_group 1;" ::: "memory")
#define CP_WAIT0()  asm volatile("cp.async.wait_group 0;" ::: "memory")

// ---------------------------------------------------------------------------
// convert fp32 -> packed fp16 (8 elements per thread)
// ---------------------------------------------------------------------------
__global__ void cvt_kernel(const float4* __restrict__ in, uint4* __restrict__ out, int n4) {
    int i = blockIdx.x * 256 + threadIdx.x;
    if (i >= n4) return;
    float4 a = in[2*i], b = in[2*i + 1];
    uint4 H;
    H.x = h2u(a.x, a.y);
    H.y = h2u(a.z, a.w);
    H.z = h2u(b.x, b.y);
    H.w = h2u(b.z, b.w);
    out[i] = H;
}

// ---------------------------------------------------------------------------
// Pooling — writes packed fp16 ctx directly
// ---------------------------------------------------------------------------
__global__ void pool_kernel(const float* __restrict__ x,
                            const float* __restrict__ wl,
                            uint32_t* __restrict__ ctx16) {
    int t = blockIdx.x;
    int b = blockIdx.y;
    int tid = threadIdx.x;
    const float* xb = x + (size_t)b * Nk * Dk;
    if (t == Tt) {
        uint32_t* dst = ctx16 + (size_t)b * Kc * (Dk/2);
        for (int dp = tid; dp < Dk/2; dp += 256)
            dst[dp] = h2u(xb[2*dp], xb[2*dp + 1]);
        return;
    }
    int gy = t >> 4, gx = t & 15;
    int n0 = 1 + (gy * 2) * 32 + gx * 2;
    int rows[4] = { n0, n0 + 1, n0 + 32, n0 + 33 };

    float p[4] = {0.f, 0.f, 0.f, 0.f};
    for (int dd = tid; dd < Dk; dd += 256) {
        float wv = wl[dd];
        p[0] += xb[(size_t)rows[0]*Dk + dd] * wv;
        p[1] += xb[(size_t)rows[1]*Dk + dd] * wv;
        p[2] += xb[(size_t)rows[2]*Dk + dd] * wv;
        p[3] += xb[(size_t)rows[3]*Dk + dd] * wv;
    }
    __shared__ float wred[4][8];
    __shared__ float sw4[4];
    int lane = tid & 31, w = tid >> 5;
    #pragma unroll
    for (int i = 0; i < 4; i++) {
        float v = p[i];
        #pragma unroll
        for (int off = 16; off; off >>= 1) v += __shfl_xor_sync(0xffffffffu, v, off);
        if (lane == 0) wred[i][w] = v;
    }
    __syncthreads();
    if (tid == 0) {
        float s[4];
        #pragma unroll
        for (int i = 0; i < 4; i++) {
            float a = 0.f;
            for (int ww = 0; ww < 8; ww++) a += wred[i][ww];
            s[i] = a;
        }
        float m = fmaxf(fmaxf(s[0], s[1]), fmaxf(s[2], s[3]));
        float e[4], su = 0.f;
        #pragma unroll
        for (int i = 0; i < 4; i++) { e[i] = expf(s[i] - m); su += e[i]; }
        float inv = 1.f / su;
        #pragma unroll
        for (int i = 0; i < 4; i++) sw4[i] = e[i] * inv;
    }
    __syncthreads();
    float w0 = sw4[0], w1 = sw4[1], w2 = sw4[2], w3 = sw4[3];
    uint32_t* dst = ctx16 + ((size_t)b * Kc + 1 + t) * (Dk/2);
    const float* r0 = xb + (size_t)rows[0]*Dk;
    const float* r1 = xb + (size_t)rows[1]*Dk;
    const float* r2 = xb + (size_t)rows[2]*Dk;
    const float* r3 = xb + (size_t)rows[3]*Dk;
    for (int dp = tid; dp < Dk/2; dp += 256) {
        int d0 = 2*dp, d1 = d0 + 1;
        float v0 = w0*r0[d0] + w1*r1[d0] + w2*r2[d0] + w3*r3[d0];
        float v1 = w0*r0[d1] + w1*r1[d1] + w2*r2[d1] + w3*r3[d1];
        dst[dp] = h2u(v0, v1);
    }
}

// ---------------------------------------------------------------------------
// CPB bias (unchanged)
// ---------------------------------------------------------------------------
__global__ void cpb_kernel(const float* __restrict__ feats, const float* __restrict__ mask,
                           const float* __restrict__ w1, const float* __restrict__ b1,
                           const float* __restrict__ w2, const float* __restrict__ b2,
                           float* __restrict__ bias) {
    __shared__ float sw1[64], sb1[32], sw2[12*32], sb2[12];
    int tid = threadIdx.x;
    if (tid < 64) sw1[tid] = w1[tid];
    if (tid >= 64 && tid < 96) sb1[tid - 64] = b1[tid - 64];
    if (tid >= 96 && tid < 108) sb2[tid - 96] = b2[tid - 96];
    for (int i = tid; i < 384; i += 256) sw2[i] = w2[i];
    __syncthreads();
    int idx = blockIdx.x * 256 + tid;
    if (idx >= NKp) return;
    float f0 = feats[2*idx], f1 = feats[2*idx + 1];
    float m = mask[idx];
    float acc[12];
    #pragma unroll
    for (int h = 0; h < 12; h++) acc[h] = sb2[h];
    #pragma unroll
    for (int j = 0; j < 32; j++) {
        float tt = f0 * sw1[2*j] + f1 * sw1[2*j + 1] + sb1[j];
        float g = 0.5f * tt * (1.0f + erff(tt * 0.7071067811865475f));
        #pragma unroll
        for (int h = 0; h < 12; h++) acc[h] += sw2[h*32 + j] * g;
    }
    #pragma unroll
    for (int h = 0; h < 12; h++) bias[(size_t)h * NKp + idx] = acc[h] * m;
}

// ---------------------------------------------------------------------------
// cp.async double-buffered fp16 GEMM, 3 CTAs/SM.
// Block 128x128, 128 threads, 4 warps in 2x2 grid, warp tile 64x64.
// K-chunk 32. ldmatrix fragments: A reused over 8 nt, B reused over 4 mt.
// ---------------------------------------------------------------------------
#define GST   20
#define AB_U32 (128*GST)               // 2560
#define STG_U32 (2*AB_U32)             // 5120
#define STG_B  (STG_U32*4)             // 20480

__global__ void __launch_bounds__(128, 3)
gemm_cp(const uint32_t* __restrict__ Ah, const uint32_t* __restrict__ Wh,
        const float* __restrict__ bias, float* __restrict__ C,
        uint32_t* __restrict__ C16,
        int M, int Nn, int Kd) {
    extern __shared__ uint32_t smu[];
    uint32_t sb = s2u(smu);
    int tid = threadIdx.x, warp = tid >> 5, lane = tid & 31;
    int wm = warp & 1, wn = warp >> 1;     // 2 x 2 warp grid, warp 64x64
    int r = lane >> 2, c = lane & 3;
    int row0 = blockIdx.y * 128, col0 = blockIdx.x * 128;
    int KPu = Kd >> 1;
    int nchk = Kd / 32;

    int la  = lane & 15;
    int lga = (lane >> 4) * 4;
    int lb  = (lane & 7) + ((lane >> 4) << 3);
    int lcb = ((lane >> 3) & 1) * 4;

    float acc[4][8][4];
    #pragma unroll
    for (int mt = 0; mt < 4; mt++)
        #pragma unroll
        for (int nt = 0; nt < 8; nt++)
            #pragma unroll
            for (int i = 0; i < 4; i++) acc[mt][nt][i] = 0.f;

    auto stage_load = [&](int s, int kcu) {
        uint32_t stb = sb + s * STG_B;
        #pragma unroll
        for (int i = 0; i < 4; i++) {          // A: 128 rows x 4 chunks of 16B
            int cid = i * 128 + tid;
            int row = cid >> 2, kj = cid & 3;
            const uint32_t* sh = Ah + (size_t)(row0 + row) * KPu + kcu + kj * 4;
            uint32_t dst = stb + (row * GST + kj * 4) * 4;
            int sz = (row0 + row < M) ? 16 : 0;
            CP16(dst, sh, sz);
        }
        #pragma unroll
        for (int i = 0; i < 4; i++) {          // B: 128 rows x 4 chunks
            int cid = i * 128 + tid;
            int row = cid >> 2, kj = cid & 3;
            const uint32_t* sh = Wh + (size_t)(col0 + row) * KPu + kcu + kj * 4;
            uint32_t dst = stb + (AB_U32 + row * GST + kj * 4) * 4;
            CP16(dst, sh, 16);
        }
        CP_COMMIT();
    };

    stage_load(0, 0);

    for (int ch = 0; ch < nchk; ch++) {
        if (ch + 1 < nchk) { stage_load((ch + 1) & 1, (ch + 1) * 16); CP_WAIT1(); }
        else               { CP_WAIT0(); }
        __syncthreads();

        uint32_t apb = sb + (ch & 1) * STG_B;
        uint32_t bpb = apb + AB_U32 * 4;

        #pragma unroll
        for (int kk = 0; kk < 2; kk++) {
            int kb = kk * 8;
            uint32_t fb[4][4];
            #pragma unroll
            for (int p = 0; p < 4; p++)
                ldsm4(fb[p], bpb + (((wn*64 + p*16 + lb) * GST) + kb + lcb) * 4);
            #pragma unroll
            for (int mt = 0; mt < 4; mt++) {
                uint32_t fa[4];
                ldsm4(fa, apb + (((wm*64 + mt*16 + la) * GST) + kb + lga) * 4);
                #pragma unroll
                for (int nt = 0; nt < 8; nt++) {
                    uint32_t b0 = fb[nt >> 1][(nt & 1) * 2];
                    uint32_t b1 = fb[nt >> 1][(nt & 1) * 2 + 1];
                    mma16h(acc[mt][nt], fa, b0, b1);
                }
            }
        }
        __syncthreads();
    }

    if (C16) {
        int Nh = Nn >> 1;
        #pragma unroll
        for (int mt = 0; mt < 4; mt++) {
            int rowa = row0 + wm * 64 + mt * 16 + r;
            #pragma unroll
            for (int nt = 0; nt < 8; nt++) {
                int cp = (col0 >> 1) + wn * 32 + nt * 4 + c;
                if (rowa < M)
                    C16[(size_t)rowa * Nh + cp] = h2u(acc[mt][nt][0], acc[mt][nt][1]);
                if (rowa + 8 < M)
                    C16[(size_t)(rowa + 8) * Nh + cp] = h2u(acc[mt][nt][2], acc[mt][nt][3]);
            }
        }
    } else {
        #pragma unroll
        for (int mt = 0; mt < 4; mt++) {
            int rowa = row0 + wm * 64 + mt * 16 + r;
            #pragma unroll
            for (int nt = 0; nt < 8; nt++) {
                int colb = col0 + wn * 64 + nt * 8 + 2 * c;
                float bv0 = bias ? bias[colb]     : 0.f;
                float bv1 = bias ? bias[colb + 1] : 0.f;
                if (rowa < M) {
                    float2 v = make_float2(acc[mt][nt][0] + bv0, acc[mt][nt][1] + bv1);
                    *(float2*)&C[(size_t)rowa * Nn + colb] = v;
                }
                if (rowa + 8 < M) {
                    float2 v = make_float2(acc[mt][nt][2] + bv0, acc[mt][nt][3] + bv1);
                    *(float2*)&C[(size_t)(rowa + 8) * Nn + colb] = v;
                }
            }
        }
    }
}

// ---------------------------------------------------------------------------
// fp16 tensor-core attention; one block per (query-tile, b*h).
// ---------------------------------------------------------------------------
#define SPQ 36
#define SPV 140

__global__ void __launch_bounds__(256)
attn_mma(const uint32_t* __restrict__ Q16, const uint32_t* __restrict__ KV16,
         const float* __restrict__ biasb, uint32_t* __restrict__ Oh) {
    extern __shared__ uint32_t sm4[];
    uint32_t* Kh = sm4;                  // [272][36]
    uint32_t* Vh = Kh + 272 * SPQ;       // [64][140]
    uint32_t* Qh = Vh + 64 * SPV;        // [128][36]
    __half* Vhb = (__half*)Vh;

    int bh = blockIdx.y;
    int b = bh / Hh, h = bh - b * Hh;
    int n0 = blockIdx.x * 128;
    int tid = threadIdx.x, wr = tid >> 5, lane = tid & 31;
    int r = lane >> 2, c = lane & 3;

    int la  = lane & 15;
    int lga = (lane >> 4) * 4;
    int lb  = (lane & 7) + ((lane >> 4) << 3);
    int lcb = ((lane >> 3) & 1) * 4;

    uint32_t kba = s2u(Kh), vba = s2u(Vh), qba = s2u(Qh);

    // K/V fill (packed fp16 source)
    const uint32_t* kvb = KV16 + (size_t)b * Kc * Dk + h * 32;
    for (int i = tid; i < 272 * 32; i += 256) {
        int kpos = i >> 5, dp = i & 31;
        uint32_t uk = 0u, uv = 0u;
        if (kpos < Kc) {
            const uint32_t* p = kvb + (size_t)kpos * Dk;
            uk = p[dp];
            uv = p[384 + dp];
        }
        Kh[kpos * SPQ + dp] = uk;
        __half2 hv = *reinterpret_cast<__half2*>(&uv);
        Vhb[(2*dp)   * 280 + kpos] = __low2half(hv);
        Vhb[(2*dp+1) * 280 + kpos] = __high2half(hv);
    }
    // Q fill
    for (int i = tid; i < 128 * 32; i += 256) {
        int rl = i >> 5, dp = i & 31;
        int n = n0 + rl; if (n > 1024) n = 1024;
        Qh[rl * SPQ + dp] = Q16[((size_t)b * Nk + n) * 384 + h * 32 + dp];
    }
    __syncthreads();

    int m0 = wr * 16;
    uint32_t qfh[4][4];
    #pragma unroll
    for (int kt = 0; kt < 4; kt++)
        ldsm4(qfh[kt], qba + ((m0 + la) * SPQ + kt*8 + lga) * 4);

    float lg[33][4];
    #pragma unroll
    for (int nt = 0; nt < 33; nt++)
        #pragma unroll
        for (int i = 0; i < 4; i++) lg[nt][i] = 0.f;

    #pragma unroll
    for (int gq = 0; gq < 8; gq++) {
        #pragma unroll
        for (int kt = 0; kt < 4; kt++) {
            uint32_t kf[2][4];
            #pragma unroll
            for (int p = 0; p < 2; p++)
                ldsm4(kf[p], kba + (((gq*4 + p*2)*8 + lb) * SPQ + kt*8 + lcb) * 4);
            #pragma unroll
            for (int x = 0; x < 4; x++) {
                uint32_t b0 = kf[x >> 1][(x & 1) * 2];
                uint32_t b1 = kf[x >> 1][(x & 1) * 2 + 1];
                mma16h(lg[gq*4 + x], qfh[kt], b0, b1);
            }
        }
    }
    #pragma unroll
    for (int kt = 0; kt < 4; kt++) {
        int kr = (32*8 + r) * SPQ + kt*8 + c;
        mma16h(lg[32], qfh[kt], Kh[kr], Kh[kr + 4]);
    }

    int nr  = n0 + m0 + r;
    int nr8 = nr + 8;
    const float* bp0 = biasb + ((size_t)h * Nk + (nr  > 1024 ? 1024 : nr )) * Kc;
    const float* bp1 = biasb + ((size_t)h * Nk + (nr8 > 1024 ? 1024 : nr8)) * Kc;
    #pragma unroll
    for (int nt = 0; nt < 33; nt++) {
        int k0 = nt*8 + 2*c, k1 = k0 + 1;
        lg[nt][0] = (k0 < Kc) ? lg[nt][0] * 0.125f + bp0[k0] : -1e30f;
        lg[nt][1] = (k1 < Kc) ? lg[nt][1] * 0.125f + bp0[k1] : -1e30f;
        lg[nt][2] = (k0 < Kc) ? lg[nt][2] * 0.125f + bp1[k0] : -1e30f;
        lg[nt][3] = (k1 < Kc) ? lg[nt][3] * 0.125f + bp1[k1] : -1e30f;
    }

    float mx0 = -1e30f, mx1 = -1e30f;
    #pragma unroll
    for (int nt = 0; nt < 33; nt++) {
        mx0 = fmaxf(mx0, fmaxf(lg[nt][0], lg[nt][1]));
        mx1 = fmaxf(mx1, fmaxf(lg[nt][2], lg[nt][3]));
    }
    mx0 = fmaxf(mx0, __shfl_xor_sync(0xffffffffu, mx0, 1));
    mx0 = fmaxf(mx0, __shfl_xor_sync(0xffffffffu, mx0, 2));
    mx1 = fmaxf(mx1, __shfl_xor_sync(0xffffffffu, mx1, 1));
    mx1 = fmaxf(mx1, __shfl_xor_sync(0xffffffffu, mx1, 2));
    float s0 = 0.f, s1 = 0.f;
    #pragma unroll
    for (int nt = 0; nt < 33; nt++) {
        lg[nt][0] = __expf(lg[nt][0] - mx0); s0 += lg[nt][0];
        lg[nt][1] = __expf(lg[nt][1] - mx0); s0 += lg[nt][1];
        lg[nt][2] = __expf(lg[nt][2] - mx1); s1 += lg[nt][2];
        lg[nt][3] = __expf(lg[nt][3] - mx1); s1 += lg[nt][3];
    }
    s0 += __shfl_xor_sync(0xffffffffu, s0, 1);
    s0 += __shfl_xor_sync(0xffffffffu, s0, 2);
    s1 += __shfl_xor_sync(0xffffffffu, s1, 1);
    s1 += __shfl_xor_sync(0xffffffffu, s1, 2);
    float inv0 = 1.f / s0, inv1 = 1.f / s1;

    float oacc[8][4];
    #pragma unroll
    for (int nt = 0; nt < 8; nt++)
        #pragma unroll
        for (int i = 0; i < 4; i++) oacc[nt][i] = 0.f;

    #pragma unroll
    for (int kt2 = 0; kt2 < 17; kt2++) {
        uint32_t ph[4];
        int e0 = 2*kt2, e1 = 2*kt2 + 1;
        ph[0] = h2u(lg[e0][0], lg[e0][1]);
        ph[1] = h2u(lg[e0][2], lg[e0][3]);
        if (e1 < 33) {
            ph[2] = h2u(lg[e1][0], lg[e1][1]);
            ph[3] = h2u(lg[e1][2], lg[e1][3]);
        } else {
            ph[2] = ph[3] = 0u;
        }
        uint32_t vf[4][4];
        #pragma unroll
        for (int p = 0; p < 4; p++)
            ldsm4(vf[p], vba + ((p*16 + lb) * SPV + kt2*8 + lcb) * 4);
        #pragma unroll
        for (int nt = 0; nt < 8; nt++) {
            uint32_t b0 = vf[nt >> 1][(nt & 1) * 2];
            uint32_t b1 = vf[nt >> 1][(nt & 1) * 2 + 1];
            mma16h(oacc[nt], ph, b0, b1);
        }
    }

    bool v0 = (nr <= 1024), v1 = (nr8 <= 1024);
    size_t ro0 = ((size_t)b * Nk + nr ) * (Dk/2) + h * (dh/2);
    size_t ro1 = ((size_t)b * Nk + nr8) * (Dk/2) + h * (dh/2);
    #pragma unroll
    for (int nt = 0; nt < 8; nt++) {
        if (v0) Oh[ro0 + nt*4 + c] = h2u(oacc[nt][0] * inv0, oacc[nt][1] * inv0);
        if (v1) Oh[ro1 + nt*4 + c] = h2u(oacc[nt][2] * inv1, oacc[nt][3] * inv1);
    }
}

// ---------------------------------------------------------------------------
// Launch
// ---------------------------------------------------------------------------
extern "C" void kernel_launch(void* const* d_in, const int* in_sizes, int n_in,
                              void* d_out, int out_size) {
    const float* x       = (const float*)d_in[0];
    const float* W_logit = (const float*)d_in[1];
    const float* Wq      = (const float*)d_in[2];
    const float* Wkv     = (const float*)d_in[3];
    const float* Wo      = (const float*)d_in[4];
    const float* bo      = (const float*)d_in[5];
    const float* cw1     = (const float*)d_in[6];
    const float* cb1     = (const float*)d_in[7];
    const float* cw2     = (const float*)d_in[8];
    const float* cb2     = (const float*)d_in[9];
    const float* feats   = (const float*)d_in[10];
    const float* maskp   = (const float*)d_in[11];
    float* out = (float*)d_out;

    float *biasb;
    uint32_t *xh, *ch, *q16, *kv16, *oh, *wqh, *wkvh, *woh;
    cudaGetSymbolAddress((void**)&biasb, g_bias);
    cudaGetSymbolAddress((void**)&xh,   g_xh);
    cudaGetSymbolAddress((void**)&ch,   g_ch);
    cudaGetSymbolAddress((void**)&q16,  g_q16);
    cudaGetSymbolAddress((void**)&kv16, g_kv16);
    cudaGetSymbolAddress((void**)&oh,   g_oh);
    cudaGetSymbolAddress((void**)&wqh,  g_wqh);
    cudaGetSymbolAddress((void**)&wkvh, g_wkvh);
    cudaGetSymbolAddress((void**)&woh,  g_woh);

    const int GEMM_SMEM = 2 * STG_B;   // 40960
    cudaFuncSetAttribute(gemm_cp, cudaFuncAttributeMaxDynamicSharedMemorySize, GEMM_SMEM);

    int n4q  = Dk * Dk / 8;
    int n4kv = 2 * Dk * Dk / 8;
    int n4x  = MQ * Dk / 8;

    cvt_kernel<<<(n4x + 255)/256, 256>>>((const float4*)x, (uint4*)xh, n4x);
    cvt_kernel<<<(n4q + 255)/256, 256>>>((const float4*)Wq, (uint4*)wqh, n4q);
    pool_kernel<<<dim3(Tt + 1, Bk), 256>>>(x, W_logit, ch);
    // Q = x @ Wq^T  -> fp16 packed
    gemm_cp<<<dim3(Dk/128, (MQ + 127)/128), 128, GEMM_SMEM>>>(xh, wqh, nullptr, nullptr, q16, MQ, Dk, Dk);
    cvt_kernel<<<(n4kv + 255)/256, 256>>>((const float4*)Wkv, (uint4*)wkvh, n4kv);
    cvt_kernel<<<(n4q + 255)/256, 256>>>((const float4*)Wo, (uint4*)woh, n4q);
    cpb_kernel<<<(NKp + 255) / 256, 256>>>(feats, maskp, cw1, cb1, cw2, cb2, biasb);
    // KV = ctx @ Wkv^T -> fp16 packed
    gemm_cp<<<dim3((2*Dk)/128, (MKV + 127)/128), 128, GEMM_SMEM>>>(ch, wkvh, nullptr, nullptr, kv16, MKV, 2*Dk, Dk);

    const size_t ATTN_SMEM = (size_t)(272*SPQ + 64*SPV + 128*SPQ) * sizeof(uint32_t); // 93440
    cudaFuncSetAttribute(attn_mma, cudaFuncAttributeMaxDynamicSharedMemorySize, (int)ATTN_SMEM);
    attn_mma<<<dim3(9, Bk * Hh), 256, ATTN_SMEM>>>(q16, kv16, biasb, oh);

    // out = O @ Wo^T + bo  (fp32)
    gemm_cp<<<dim3(Dk/128, (MQ + 127)/128), 128, GEMM_SMEM>>>(oh, woh, bo, out, nullptr, MQ, Dk, Dk);
}

// round 15
// speedup vs baseline: 1.2581x; 1.2581x over previous
#include <cuda_runtime.h>
#include <cuda_fp16.h>
#include <cstdint>

// Problem constants
#define Bk   32
#define Nk   1025
#define Dk   768
#define Hh   12
#define dh   64
#define Tt   256
#define Kc   257
#define NKp  (Nk*Kc)
#define MQ   (Bk*Nk)      // 32800
#define MKV  (Bk*Kc)      // 8224

// Scratch (device globals) — fp16 packed operands (uint32 = 2 consecutive elems)
__device__ float    g_bias[(size_t)Hh*NKp];
__device__ uint32_t g_xh  [MQ*Dk/2];
__device__ uint32_t g_ch  [MKV*Dk/2];     // pooled context, fp16 packed
__device__ uint32_t g_q16 [MQ*Dk/2];      // Q projection, fp16 packed
__device__ uint32_t g_kv16[MKV*Dk];       // KV projection, fp16 packed
__device__ uint32_t g_oh  [MQ*Dk/2];      // attention output, fp16 packed
__device__ uint32_t g_wqh [Dk*Dk/2];
__device__ uint32_t g_wkvh[Dk*Dk];
__device__ uint32_t g_woh [Dk*Dk/2];

// ---------------------------------------------------------------------------
// helpers
// ---------------------------------------------------------------------------
__device__ __forceinline__ uint32_t h2u(float f0, float f1) {
    __half2 h = __floats2half2_rn(f0, f1);
    return *reinterpret_cast<uint32_t*>(&h);
}
__device__ __forceinline__ void mma16h(float* d, const uint32_t* a, uint32_t b0, uint32_t b1) {
    asm volatile(
        "mma.sync.aligned.m16n8k16.row.col.f32.f16.f16.f32 "
        "{%0,%1,%2,%3}, {%4,%5,%6,%7}, {%8,%9}, {%0,%1,%2,%3};"
        : "+f"(d[0]), "+f"(d[1]), "+f"(d[2]), "+f"(d[3])
        : "r"(a[0]), "r"(a[1]), "r"(a[2]), "r"(a[3]), "r"(b0), "r"(b1));
}
__device__ __forceinline__ void ldsm4(uint32_t* d, uint32_t addr) {
    asm volatile("ldmatrix.sync.aligned.m8n8.x4.shared.b16 {%0,%1,%2,%3}, [%4];"
        : "=r"(d[0]), "=r"(d[1]), "=r"(d[2]), "=r"(d[3]) : "r"(addr));
}
__device__ __forceinline__ uint32_t s2u(const void* p) {
    uint32_t a;
    asm("{ .reg .u64 t; cvta.to.shared.u64 t, %1; cvt.u32.u64 %0, t; }" : "=r"(a) : "l"(p));
    return a;
}
#define CP16(dst, src, sz) \
    asm volatile("cp.async.cg.shared.global [%0], [%1], 16, %2;" \
                 :: "r"(dst), "l"(src), "r"(sz) : "memory")
#define CP_COMMIT() asm volatile("cp.async.commit_group;" ::: "memory")
#define CP_WAIT1()  asm volatile("cp.async.wait_group 1;" ::: "memory")
#define CP_WAIT0()  asm volatile("cp.async.wait_group 0;" ::: "memory")

// ---------------------------------------------------------------------------
// convert fp32 -> packed fp16 (8 elements per thread)
// ---------------------------------------------------------------------------
__global__ void cvt_kernel(const float4* __restrict__ in, uint4* __restrict__ out, int n4) {
    int i = blockIdx.x * 256 + threadIdx.x;
    if (i >= n4) return;
    float4 a = in[2*i], b = in[2*i + 1];
    uint4 H;
    H.x = h2u(a.x, a.y);
    H.y = h2u(a.z, a.w);
    H.z = h2u(b.x, b.y);
    H.w = h2u(b.z, b.w);
    out[i] = H;
}

// ---------------------------------------------------------------------------
// Pooling — writes packed fp16 ctx directly
// ---------------------------------------------------------------------------
__global__ void pool_kernel(const float* __restrict__ x,
                            const float* __restrict__ wl,
                            uint32_t* __restrict__ ctx16) {
    int t = blockIdx.x;
    int b = blockIdx.y;
    int tid = threadIdx.x;
    const float* xb = x + (size_t)b * Nk * Dk;
    if (t == Tt) {
        uint32_t* dst = ctx16 + (size_t)b * Kc * (Dk/2);
        for (int dp = tid; dp < Dk/2; dp += 256)
            dst[dp] = h2u(xb[2*dp], xb[2*dp + 1]);
        return;
    }
    int gy = t >> 4, gx = t & 15;
    int n0 = 1 + (gy * 2) * 32 + gx * 2;
    int rows[4] = { n0, n0 + 1, n0 + 32, n0 + 33 };

    float p[4] = {0.f, 0.f, 0.f, 0.f};
    for (int dd = tid; dd < Dk; dd += 256) {
        float wv = wl[dd];
        p[0] += xb[(size_t)rows[0]*Dk + dd] * wv;
        p[1] += xb[(size_t)rows[1]*Dk + dd] * wv;
        p[2] += xb[(size_t)rows[2]*Dk + dd] * wv;
        p[3] += xb[(size_t)rows[3]*Dk + dd] * wv;
    }
    __shared__ float wred[4][8];
    __shared__ float sw4[4];
    int lane = tid & 31, w = tid >> 5;
    #pragma unroll
    for (int i = 0; i < 4; i++) {
        float v = p[i];
        #pragma unroll
        for (int off = 16; off; off >>= 1) v += __shfl_xor_sync(0xffffffffu, v, off);
        if (lane == 0) wred[i][w] = v;
    }
    __syncthreads();
    if (tid == 0) {
        float s[4];
        #pragma unroll
        for (int i = 0; i < 4; i++) {
            float a = 0.f;
            for (int ww = 0; ww < 8; ww++) a += wred[i][ww];
            s[i] = a;
        }
        float m = fmaxf(fmaxf(s[0], s[1]), fmaxf(s[2], s[3]));
        float e[4], su = 0.f;
        #pragma unroll
        for (int i = 0; i < 4; i++) { e[i] = expf(s[i] - m); su += e[i]; }
        float inv = 1.f / su;
        #pragma unroll
        for (int i = 0; i < 4; i++) sw4[i] = e[i] * inv;
    }
    __syncthreads();
    float w0 = sw4[0], w1 = sw4[1], w2 = sw4[2], w3 = sw4[3];
    uint32_t* dst = ctx16 + ((size_t)b * Kc + 1 + t) * (Dk/2);
    const float* r0 = xb + (size_t)rows[0]*Dk;
    const float* r1 = xb + (size_t)rows[1]*Dk;
    const float* r2 = xb + (size_t)rows[2]*Dk;
    const float* r3 = xb + (size_t)rows[3]*Dk;
    for (int dp = tid; dp < Dk/2; dp += 256) {
        int d0 = 2*dp, d1 = d0 + 1;
        float v0 = w0*r0[d0] + w1*r1[d0] + w2*r2[d0] + w3*r3[d0];
        float v1 = w0*r0[d1] + w1*r1[d1] + w2*r2[d1] + w3*r3[d1];
        dst[dp] = h2u(v0, v1);
    }
}

// ---------------------------------------------------------------------------
// CPB bias (unchanged)
// ---------------------------------------------------------------------------
__global__ void cpb_kernel(const float* __restrict__ feats, const float* __restrict__ mask,
                           const float* __restrict__ w1, const float* __restrict__ b1,
                           const float* __restrict__ w2, const float* __restrict__ b2,
                           float* __restrict__ bias) {
    __shared__ float sw1[64], sb1[32], sw2[12*32], sb2[12];
    int tid = threadIdx.x;
    if (tid < 64) sw1[tid] = w1[tid];
    if (tid >= 64 && tid < 96) sb1[tid - 64] = b1[tid - 64];
    if (tid >= 96 && tid < 108) sb2[tid - 96] = b2[tid - 96];
    for (int i = tid; i < 384; i += 256) sw2[i] = w2[i];
    __syncthreads();
    int idx = blockIdx.x * 256 + tid;
    if (idx >= NKp) return;
    float f0 = feats[2*idx], f1 = feats[2*idx + 1];
    float m = mask[idx];
    float acc[12];
    #pragma unroll
    for (int h = 0; h < 12; h++) acc[h] = sb2[h];
    #pragma unroll
    for (int j = 0; j < 32; j++) {
        float tt = f0 * sw1[2*j] + f1 * sw1[2*j + 1] + sb1[j];
        float g = 0.5f * tt * (1.0f + erff(tt * 0.7071067811865475f));
        #pragma unroll
        for (int h = 0; h < 12; h++) acc[h] += sw2[h*32 + j] * g;
    }
    #pragma unroll
    for (int h = 0; h < 12; h++) bias[(size_t)h * NKp + idx] = acc[h] * m;
}

// ---------------------------------------------------------------------------
// cp.async double-buffered fp16 GEMM, 2 CTAs/SM, ldmatrix fragments.
// Block 128x128, K-chunk 32, 256 threads, 8 warps 2x4, warp 64x32. (R13 config)
// Output: fp32 (+bias) if C16==null, else packed fp16.
// ---------------------------------------------------------------------------
#define GST   20
#define AB_U32 (128*GST)               // 2560
#define BB_U32 (128*GST)               // 2560
#define STG_U32 (AB_U32 + BB_U32)      // 5120
#define STG_B  (STG_U32*4)             // 20480

__global__ void __launch_bounds__(256, 2)
gemm_cp(const uint32_t* __restrict__ Ah, const uint32_t* __restrict__ Wh,
        const float* __restrict__ bias, float* __restrict__ C,
        uint32_t* __restrict__ C16,
        int M, int Nn, int Kd) {
    extern __shared__ uint32_t smu[];
    uint32_t sb = s2u(smu);
    int tid = threadIdx.x, warp = tid >> 5, lane = tid & 31;
    int wm = warp & 1, wn = warp >> 1;     // 2 x 4 warp grid
    int r = lane >> 2, c = lane & 3;
    int row0 = blockIdx.y * 128, col0 = blockIdx.x * 128;
    int KPu = Kd >> 1;
    int nchk = Kd / 32;

    int la  = lane & 15;
    int lga = (lane >> 4) * 4;
    int lb  = (lane & 7) + ((lane >> 4) << 3);
    int lcb = ((lane >> 3) & 1) * 4;

    float acc[4][4][4];
    #pragma unroll
    for (int mt = 0; mt < 4; mt++)
        #pragma unroll
        for (int nt = 0; nt < 4; nt++)
            #pragma unroll
            for (int i = 0; i < 4; i++) acc[mt][nt][i] = 0.f;

    auto stage_load = [&](int s, int kcu) {
        uint32_t stb = sb + s * STG_B;
        #pragma unroll
        for (int i = 0; i < 2; i++) {
            int cid = i * 256 + tid;
            int row = cid >> 2, kj = cid & 3;
            const uint32_t* sh = Ah + (size_t)(row0 + row) * KPu + kcu + kj * 4;
            uint32_t dst = stb + (row * GST + kj * 4) * 4;
            int sz = (row0 + row < M) ? 16 : 0;
            CP16(dst, sh, sz);
        }
        #pragma unroll
        for (int i = 0; i < 2; i++) {
            int cid = i * 256 + tid;
            int row = cid >> 2, kj = cid & 3;
            const uint32_t* sh = Wh + (size_t)(col0 + row) * KPu + kcu + kj * 4;
            uint32_t dst = stb + (AB_U32 + row * GST + kj * 4) * 4;
            CP16(dst, sh, 16);
        }
        CP_COMMIT();
    };

    stage_load(0, 0);

    for (int ch = 0; ch < nchk; ch++) {
        if (ch + 1 < nchk) { stage_load((ch + 1) & 1, (ch + 1) * 16); CP_WAIT1(); }
        else               { CP_WAIT0(); }
        __syncthreads();

        uint32_t apb = sb + (ch & 1) * STG_B;
        uint32_t bpb = apb + AB_U32 * 4;

        #pragma unroll
        for (int kk = 0; kk < 2; kk++) {
            int kb = kk * 8;
            uint32_t fah[4][4];
            #pragma unroll
            for (int mt = 0; mt < 4; mt++)
                ldsm4(fah[mt], apb + (((wm*64 + mt*16 + la) * GST) + kb + lga) * 4);
            uint32_t fb[2][4];
            #pragma unroll
            for (int p = 0; p < 2; p++)
                ldsm4(fb[p], bpb + (((wn*32 + p*16 + lb) * GST) + kb + lcb) * 4);
            #pragma unroll
            for (int nt = 0; nt < 4; nt++) {
                uint32_t b0 = fb[nt >> 1][(nt & 1) * 2];
                uint32_t b1 = fb[nt >> 1][(nt & 1) * 2 + 1];
                #pragma unroll
                for (int mt = 0; mt < 4; mt++) mma16h(acc[mt][nt], fah[mt], b0, b1);
            }
        }
        __syncthreads();
    }

    if (C16) {
        int Nh = Nn >> 1;
        #pragma unroll
        for (int mt = 0; mt < 4; mt++) {
            int rowa = row0 + wm * 64 + mt * 16 + r;
            #pragma unroll
            for (int nt = 0; nt < 4; nt++) {
                int cp = (col0 >> 1) + wn * 16 + nt * 4 + c;
                if (rowa < M)
                    C16[(size_t)rowa * Nh + cp] = h2u(acc[mt][nt][0], acc[mt][nt][1]);
                if (rowa + 8 < M)
                    C16[(size_t)(rowa + 8) * Nh + cp] = h2u(acc[mt][nt][2], acc[mt][nt][3]);
            }
        }
    } else {
        #pragma unroll
        for (int mt = 0; mt < 4; mt++) {
            int rowa = row0 + wm * 64 + mt * 16 + r;
            #pragma unroll
            for (int nt = 0; nt < 4; nt++) {
                int colb = col0 + wn * 32 + nt * 8 + 2 * c;
                float bv0 = bias ? bias[colb]     : 0.f;
                float bv1 = bias ? bias[colb + 1] : 0.f;
                if (rowa < M) {
                    float2 v = make_float2(acc[mt][nt][0] + bv0, acc[mt][nt][1] + bv1);
                    *(float2*)&C[(size_t)rowa * Nn + colb] = v;
                }
                if (rowa + 8 < M) {
                    float2 v = make_float2(acc[mt][nt][2] + bv0, acc[mt][nt][3] + bv1);
                    *(float2*)&C[(size_t)(rowa + 8) * Nn + colb] = v;
                }
            }
        }
    }
}

// ---------------------------------------------------------------------------
// fp16 tensor-core attention; grid (3, B*H): K/V staged once per block,
// 3 query tiles processed serially (tail-wave fix over R13's 9-tile loop).
// ---------------------------------------------------------------------------
#define SPQ 36
#define SPV 140

__global__ void __launch_bounds__(256)
attn_mma(const uint32_t* __restrict__ Q16, const uint32_t* __restrict__ KV16,
         const float* __restrict__ biasb, uint32_t* __restrict__ Oh) {
    extern __shared__ uint32_t sm4[];
    uint32_t* Kh = sm4;                  // [272][36]
    uint32_t* Vh = Kh + 272 * SPQ;       // [64][140]
    uint32_t* Qh = Vh + 64 * SPV;        // [128][36]
    __half* Vhb = (__half*)Vh;

    int bh = blockIdx.y;
    int b = bh / Hh, h = bh - b * Hh;
    int tid = threadIdx.x, wr = tid >> 5, lane = tid & 31;
    int r = lane >> 2, c = lane & 3;

    int la  = lane & 15;
    int lga = (lane >> 4) * 4;
    int lb  = (lane & 7) + ((lane >> 4) << 3);
    int lcb = ((lane >> 3) & 1) * 4;

    uint32_t kba = s2u(Kh), vba = s2u(Vh), qba = s2u(Qh);

    // K/V fill (packed fp16 source)
    const uint32_t* kvb = KV16 + (size_t)b * Kc * Dk + h * 32;
    for (int i = tid; i < 272 * 32; i += 256) {
        int kpos = i >> 5, dp = i & 31;
        uint32_t uk = 0u, uv = 0u;
        if (kpos < Kc) {
            const uint32_t* p = kvb + (size_t)kpos * Dk;
            uk = p[dp];
            uv = p[384 + dp];
        }
        Kh[kpos * SPQ + dp] = uk;
        __half2 hv = *reinterpret_cast<__half2*>(&uv);
        Vhb[(2*dp)   * 280 + kpos] = __low2half(hv);
        Vhb[(2*dp+1) * 280 + kpos] = __high2half(hv);
    }

    #pragma unroll 1
    for (int j = 0; j < 3; j++) {
        int n0 = (blockIdx.x * 3 + j) * 128;
        __syncthreads();   // Q smem reuse barrier (also covers first-iter K/V fill)
        for (int i = tid; i < 128 * 32; i += 256) {
            int rl = i >> 5, dp = i & 31;
            int n = n0 + rl; if (n > 1024) n = 1024;
            Qh[rl * SPQ + dp] = Q16[((size_t)b * Nk + n) * 384 + h * 32 + dp];
        }
        __syncthreads();

        int m0 = wr * 16;
        uint32_t qfh[4][4];
        #pragma unroll
        for (int kt = 0; kt < 4; kt++)
            ldsm4(qfh[kt], qba + ((m0 + la) * SPQ + kt*8 + lga) * 4);

        float lg[33][4];
        #pragma unroll
        for (int nt = 0; nt < 33; nt++)
            #pragma unroll
            for (int i = 0; i < 4; i++) lg[nt][i] = 0.f;

        #pragma unroll
        for (int gq = 0; gq < 8; gq++) {
            #pragma unroll
            for (int kt = 0; kt < 4; kt++) {
                uint32_t kf[2][4];
                #pragma unroll
                for (int p = 0; p < 2; p++)
                    ldsm4(kf[p], kba + (((gq*4 + p*2)*8 + lb) * SPQ + kt*8 + lcb) * 4);
                #pragma unroll
                for (int x = 0; x < 4; x++) {
                    uint32_t b0 = kf[x >> 1][(x & 1) * 2];
                    uint32_t b1 = kf[x >> 1][(x & 1) * 2 + 1];
                    mma16h(lg[gq*4 + x], qfh[kt], b0, b1);
                }
            }
        }
        #pragma unroll
        for (int kt = 0; kt < 4; kt++) {
            int kr = (32*8 + r) * SPQ + kt*8 + c;
            mma16h(lg[32], qfh[kt], Kh[kr], Kh[kr + 4]);
        }

        int nr  = n0 + m0 + r;
        int nr8 = nr + 8;
        const float* bp0 = biasb + ((size_t)h * Nk + (nr  > 1024 ? 1024 : nr )) * Kc;
        const float* bp1 = biasb + ((size_t)h * Nk + (nr8 > 1024 ? 1024 : nr8)) * Kc;
        #pragma unroll
        for (int nt = 0; nt < 33; nt++) {
            int k0 = nt*8 + 2*c, k1 = k0 + 1;
            lg[nt][0] = (k0 < Kc) ? lg[nt][0] * 0.125f + bp0[k0] : -1e30f;
            lg[nt][1] = (k1 < Kc) ? lg[nt][1] * 0.125f + bp0[k1] : -1e30f;
            lg[nt][2] = (k0 < Kc) ? lg[nt][2] * 0.125f + bp1[k0] : -1e30f;
            lg[nt][3] = (k1 < Kc) ? lg[nt][3] * 0.125f + bp1[k1] : -1e30f;
        }

        float mx0 = -1e30f, mx1 = -1e30f;
        #pragma unroll
        for (int nt = 0; nt < 33; nt++) {
            mx0 = fmaxf(mx0, fmaxf(lg[nt][0], lg[nt][1]));
            mx1 = fmaxf(mx1, fmaxf(lg[nt][2], lg[nt][3]));
        }
        mx0 = fmaxf(mx0, __shfl_xor_sync(0xffffffffu, mx0, 1));
        mx0 = fmaxf(mx0, __shfl_xor_sync(0xffffffffu, mx0, 2));
        mx1 = fmaxf(mx1, __shfl_xor_sync(0xffffffffu, mx1, 1));
        mx1 = fmaxf(mx1, __shfl_xor_sync(0xffffffffu, mx1, 2));
        float s0 = 0.f, s1 = 0.f;
        #pragma unroll
        for (int nt = 0; nt < 33; nt++) {
            lg[nt][0] = __expf(lg[nt][0] - mx0); s0 += lg[nt][0];
            lg[nt][1] = __expf(lg[nt][1] - mx0); s0 += lg[nt][1];
            lg[nt][2] = __expf(lg[nt][2] - mx1); s1 += lg[nt][2];
            lg[nt][3] = __expf(lg[nt][3] - mx1); s1 += lg[nt][3];
        }
        s0 += __shfl_xor_sync(0xffffffffu, s0, 1);
        s0 += __shfl_xor_sync(0xffffffffu, s0, 2);
        s1 += __shfl_xor_sync(0xffffffffu, s1, 1);
        s1 += __shfl_xor_sync(0xffffffffu, s1, 2);
        float inv0 = 1.f / s0, inv1 = 1.f / s1;

        float oacc[8][4];
        #pragma unroll
        for (int nt = 0; nt < 8; nt++)
            #pragma unroll
            for (int i = 0; i < 4; i++) oacc[nt][i] = 0.f;

        #pragma unroll
        for (int kt2 = 0; kt2 < 17; kt2++) {
            uint32_t ph[4];
            int e0 = 2*kt2, e1 = 2*kt2 + 1;
            ph[0] = h2u(lg[e0][0], lg[e0][1]);
            ph[1] = h2u(lg[e0][2], lg[e0][3]);
            if (e1 < 33) {
                ph[2] = h2u(lg[e1][0], lg[e1][1]);
                ph[3] = h2u(lg[e1][2], lg[e1][3]);
            } else {
                ph[2] = ph[3] = 0u;
            }
            uint32_t vf[4][4];
            #pragma unroll
            for (int p = 0; p < 4; p++)
                ldsm4(vf[p], vba + ((p*16 + lb) * SPV + kt2*8 + lcb) * 4);
            #pragma unroll
            for (int nt = 0; nt < 8; nt++) {
                uint32_t b0 = vf[nt >> 1][(nt & 1) * 2];
                uint32_t b1 = vf[nt >> 1][(nt & 1) * 2 + 1];
                mma16h(oacc[nt], ph, b0, b1);
            }
        }

        bool v0 = (nr <= 1024), v1 = (nr8 <= 1024);
        size_t ro0 = ((size_t)b * Nk + nr ) * (Dk/2) + h * (dh/2);
        size_t ro1 = ((size_t)b * Nk + nr8) * (Dk/2) + h * (dh/2);
        #pragma unroll
        for (int nt = 0; nt < 8; nt++) {
            if (v0) Oh[ro0 + nt*4 + c] = h2u(oacc[nt][0] * inv0, oacc[nt][1] * inv0);
            if (v1) Oh[ro1 + nt*4 + c] = h2u(oacc[nt][2] * inv1, oacc[nt][3] * inv1);
        }
    }
}

// ---------------------------------------------------------------------------
// Launch
// ---------------------------------------------------------------------------
extern "C" void kernel_launch(void* const* d_in, const int* in_sizes, int n_in,
                              void* d_out, int out_size) {
    const float* x       = (const float*)d_in[0];
    const float* W_logit = (const float*)d_in[1];
    const float* Wq      = (const float*)d_in[2];
    const float* Wkv     = (const float*)d_in[3];
    const float* Wo      = (const float*)d_in[4];
    const float* bo      = (const float*)d_in[5];
    const float* cw1     = (const float*)d_in[6];
    const float* cb1     = (const float*)d_in[7];
    const float* cw2     = (const float*)d_in[8];
    const float* cb2     = (const float*)d_in[9];
    const float* feats   = (const float*)d_in[10];
    const float* maskp   = (const float*)d_in[11];
    float* out = (float*)d_out;

    float *biasb;
    uint32_t *xh, *ch, *q16, *kv16, *oh, *wqh, *wkvh, *woh;
    cudaGetSymbolAddress((void**)&biasb, g_bias);
    cudaGetSymbolAddress((void**)&xh,   g_xh);
    cudaGetSymbolAddress((void**)&ch,   g_ch);
    cudaGetSymbolAddress((void**)&q16,  g_q16);
    cudaGetSymbolAddress((void**)&kv16, g_kv16);
    cudaGetSymbolAddress((void**)&oh,   g_oh);
    cudaGetSymbolAddress((void**)&wqh,  g_wqh);
    cudaGetSymbolAddress((void**)&wkvh, g_wkvh);
    cudaGetSymbolAddress((void**)&woh,  g_woh);

    const int GEMM_SMEM = 2 * STG_B;   // 40960
    cudaFuncSetAttribute(gemm_cp, cudaFuncAttributeMaxDynamicSharedMemorySize, GEMM_SMEM);

    int n4q  = Dk * Dk / 8;
    int n4kv = 2 * Dk * Dk / 8;
    int n4x  = MQ * Dk / 8;

    cvt_kernel<<<(n4x + 255)/256, 256>>>((const float4*)x, (uint4*)xh, n4x);
    cvt_kernel<<<(n4q + 255)/256, 256>>>((const float4*)Wq, (uint4*)wqh, n4q);
    pool_kernel<<<dim3(Tt + 1, Bk), 256>>>(x, W_logit, ch);
    // Q = x @ Wq^T  -> fp16 packed
    gemm_cp<<<dim3(Dk/128, (MQ + 127)/128), 256, GEMM_SMEM>>>(xh, wqh, nullptr, nullptr, q16, MQ, Dk, Dk);
    cvt_kernel<<<(n4kv + 255)/256, 256>>>((const float4*)Wkv, (uint4*)wkvh, n4kv);
    cvt_kernel<<<(n4q + 255)/256, 256>>>((const float4*)Wo, (uint4*)woh, n4q);
    cpb_kernel<<<(NKp + 255) / 256, 256>>>(feats, maskp, cw1, cb1, cw2, cb2, biasb);
    // KV = ctx @ Wkv^T -> fp16 packed
    gemm_cp<<<dim3((2*Dk)/128, (MKV + 127)/128), 256, GEMM_SMEM>>>(ch, wkvh, nullptr, nullptr, kv16, MKV, 2*Dk, Dk);

    const size_t ATTN_SMEM = (size_t)(272*SPQ + 64*SPV + 128*SPQ) * sizeof(uint32_t); // 93440
    cudaFuncSetAttribute(attn_mma, cudaFuncAttributeMaxDynamicSharedMemorySize, (int)ATTN_SMEM);
    attn_mma<<<dim3(3, Bk * Hh), 256, ATTN_SMEM>>>(q16, kv16, biasb, oh);

    // out = O @ Wo^T + bo  (fp32)
    gemm_cp<<<dim3(Dk/128, (MQ + 127)/128), 256, GEMM_SMEM>>>(oh, woh, bo, out, nullptr, MQ, Dk, Dk);
}

// round 16
// speedup vs baseline: 1.3357x; 1.0617x over previous
#include <cuda_runtime.h>
#include <cuda_fp16.h>
#include <cstdint>

// Problem constants
#define Bk   32
#define Nk   1025
#define Dk   768
#define Hh   12
#define dh   64
#define Tt   256
#define Kc   257
#define NKp  (Nk*Kc)
#define MQ   (Bk*Nk)      // 32800
#define MKV  (Bk*Kc)      // 8224
#define KB2  264          // padded bias row (halves), covers k0 up to 262

// Scratch (device globals)
__device__ __half   g_bias16[(size_t)Hh*Nk*KB2];
__device__ uint32_t g_xh  [MQ*Dk/2];
__device__ uint32_t g_ch  [MKV*Dk/2];
__device__ uint32_t g_q16 [MQ*Dk/2];
__device__ uint32_t g_kv16[MKV*Dk];
__device__ uint32_t g_oh  [MQ*Dk/2];
__device__ uint32_t g_wqh [Dk*Dk/2];
__device__ uint32_t g_wkvh[Dk*Dk];
__device__ uint32_t g_woh [Dk*Dk/2];

// ---------------------------------------------------------------------------
// helpers
// ---------------------------------------------------------------------------
__device__ __forceinline__ uint32_t h2u(float f0, float f1) {
    __half2 h = __floats2half2_rn(f0, f1);
    return *reinterpret_cast<uint32_t*>(&h);
}
__device__ __forceinline__ void mma16h(float* d, const uint32_t* a, uint32_t b0, uint32_t b1) {
    asm volatile(
        "mma.sync.aligned.m16n8k16.row.col.f32.f16.f16.f32 "
        "{%0,%1,%2,%3}, {%4,%5,%6,%7}, {%8,%9}, {%0,%1,%2,%3};"
        : "+f"(d[0]), "+f"(d[1]), "+f"(d[2]), "+f"(d[3])
        : "r"(a[0]), "r"(a[1]), "r"(a[2]), "r"(a[3]), "r"(b0), "r"(b1));
}
__device__ __forceinline__ void ldsm4(uint32_t* d, uint32_t addr) {
    asm volatile("ldmatrix.sync.aligned.m8n8.x4.shared.b16 {%0,%1,%2,%3}, [%4];"
        : "=r"(d[0]), "=r"(d[1]), "=r"(d[2]), "=r"(d[3]) : "r"(addr));
}
__device__ __forceinline__ uint32_t s2u(const void* p) {
    uint32_t a;
    asm("{ .reg .u64 t; cvta.to.shared.u64 t, %1; cvt.u32.u64 %0, t; }" : "=r"(a) : "l"(p));
    return a;
}
#define CP16(dst, src, sz) \
    asm volatile("cp.async.cg.shared.global [%0], [%1], 16, %2;" \
                 :: "r"(dst), "l"(src), "r"(sz) : "memory")
#define CP_COMMIT() asm volatile("cp.async.commit_group;" ::: "memory")
#define CP_WAIT2()  asm volatile("cp.async.wait_group 2;" ::: "memory")
#define CP_WAIT1()  asm volatile("cp.async.wait_group 1;" ::: "memory")
#define CP_WAIT0()  asm volatile("cp.async.wait_group 0;" ::: "memory")

// ---------------------------------------------------------------------------
// convert fp32 -> packed fp16
// ---------------------------------------------------------------------------
__global__ void cvt_kernel(const float4* __restrict__ in, uint4* __restrict__ out, int n4) {
    int i = blockIdx.x * 256 + threadIdx.x;
    if (i >= n4) return;
    float4 a = in[2*i], b = in[2*i + 1];
    uint4 H;
    H.x = h2u(a.x, a.y);
    H.y = h2u(a.z, a.w);
    H.z = h2u(b.x, b.y);
    H.w = h2u(b.z, b.w);
    out[i] = H;
}

// ---------------------------------------------------------------------------
// Pooling — writes packed fp16 ctx
// ---------------------------------------------------------------------------
__global__ void pool_kernel(const float* __restrict__ x,
                            const float* __restrict__ wl,
                            uint32_t* __restrict__ ctx16) {
    int t = blockIdx.x;
    int b = blockIdx.y;
    int tid = threadIdx.x;
    const float* xb = x + (size_t)b * Nk * Dk;
    if (t == Tt) {
        uint32_t* dst = ctx16 + (size_t)b * Kc * (Dk/2);
        for (int dp = tid; dp < Dk/2; dp += 256)
            dst[dp] = h2u(xb[2*dp], xb[2*dp + 1]);
        return;
    }
    int gy = t >> 4, gx = t & 15;
    int n0 = 1 + (gy * 2) * 32 + gx * 2;
    int rows[4] = { n0, n0 + 1, n0 + 32, n0 + 33 };

    float p[4] = {0.f, 0.f, 0.f, 0.f};
    for (int dd = tid; dd < Dk; dd += 256) {
        float wv = wl[dd];
        p[0] += xb[(size_t)rows[0]*Dk + dd] * wv;
        p[1] += xb[(size_t)rows[1]*Dk + dd] * wv;
        p[2] += xb[(size_t)rows[2]*Dk + dd] * wv;
        p[3] += xb[(size_t)rows[3]*Dk + dd] * wv;
    }
    __shared__ float wred[4][8];
    __shared__ float sw4[4];
    int lane = tid & 31, w = tid >> 5;
    #pragma unroll
    for (int i = 0; i < 4; i++) {
        float v = p[i];
        #pragma unroll
        for (int off = 16; off; off >>= 1) v += __shfl_xor_sync(0xffffffffu, v, off);
        if (lane == 0) wred[i][w] = v;
    }
    __syncthreads();
    if (tid == 0) {
        float s[4];
        #pragma unroll
        for (int i = 0; i < 4; i++) {
            float a = 0.f;
            for (int ww = 0; ww < 8; ww++) a += wred[i][ww];
            s[i] = a;
        }
        float m = fmaxf(fmaxf(s[0], s[1]), fmaxf(s[2], s[3]));
        float e[4], su = 0.f;
        #pragma unroll
        for (int i = 0; i < 4; i++) { e[i] = expf(s[i] - m); su += e[i]; }
        float inv = 1.f / su;
        #pragma unroll
        for (int i = 0; i < 4; i++) sw4[i] = e[i] * inv;
    }
    __syncthreads();
    float w0 = sw4[0], w1 = sw4[1], w2 = sw4[2], w3 = sw4[3];
    uint32_t* dst = ctx16 + ((size_t)b * Kc + 1 + t) * (Dk/2);
    const float* r0 = xb + (size_t)rows[0]*Dk;
    const float* r1 = xb + (size_t)rows[1]*Dk;
    const float* r2 = xb + (size_t)rows[2]*Dk;
    const float* r3 = xb + (size_t)rows[3]*Dk;
    for (int dp = tid; dp < Dk/2; dp += 256) {
        int d0 = 2*dp, d1 = d0 + 1;
        float v0 = w0*r0[d0] + w1*r1[d0] + w2*r2[d0] + w3*r3[d0];
        float v1 = w0*r0[d1] + w1*r1[d1] + w2*r2[d1] + w3*r3[d1];
        dst[dp] = h2u(v0, v1);
    }
}

// ---------------------------------------------------------------------------
// CPB bias — writes fp16 into padded [H][N][KB2] table
// ---------------------------------------------------------------------------
__global__ void cpb_kernel(const float* __restrict__ feats, const float* __restrict__ mask,
                           const float* __restrict__ w1, const float* __restrict__ b1,
                           const float* __restrict__ w2, const float* __restrict__ b2,
                           __half* __restrict__ bias16) {
    __shared__ float sw1[64], sb1[32], sw2[12*32], sb2[12];
    int tid = threadIdx.x;
    if (tid < 64) sw1[tid] = w1[tid];
    if (tid >= 64 && tid < 96) sb1[tid - 64] = b1[tid - 64];
    if (tid >= 96 && tid < 108) sb2[tid - 96] = b2[tid - 96];
    for (int i = tid; i < 384; i += 256) sw2[i] = w2[i];
    __syncthreads();
    int idx = blockIdx.x * 256 + tid;
    if (idx >= NKp) return;
    int n = idx / Kc, k = idx - n * Kc;
    float f0 = feats[2*idx], f1 = feats[2*idx + 1];
    float m = mask[idx];
    float acc[12];
    #pragma unroll
    for (int h = 0; h < 12; h++) acc[h] = sb2[h];
    #pragma unroll
    for (int j = 0; j < 32; j++) {
        float tt = f0 * sw1[2*j] + f1 * sw1[2*j + 1] + sb1[j];
        float g = 0.5f * tt * (1.0f + erff(tt * 0.7071067811865475f));
        #pragma unroll
        for (int h = 0; h < 12; h++) acc[h] += sw2[h*32 + j] * g;
    }
    size_t base = (size_t)n * KB2 + k;
    #pragma unroll
    for (int h = 0; h < 12; h++)
        bias16[(size_t)h * (Nk * KB2) + base] = __float2half(acc[h] * m);
}

// ---------------------------------------------------------------------------
// cp.async 3-stage fp16 GEMM, 2 CTAs/SM, ldmatrix fragments.
// Block 128x128, K-chunk 32, 256 threads, 8 warps 2x4, warp 64x32.
// ---------------------------------------------------------------------------
#define GST   20
#define AB_U32 (128*GST)               // 2560
#define BB_U32 (128*GST)               // 2560
#define STG_U32 (AB_U32 + BB_U32)      // 5120
#define STG_B  (STG_U32*4)             // 20480

__global__ void __launch_bounds__(256, 2)
gemm_cp(const uint32_t* __restrict__ Ah, const uint32_t* __restrict__ Wh,
        const float* __restrict__ bias, float* __restrict__ C,
        uint32_t* __restrict__ C16,
        int M, int Nn, int Kd) {
    extern __shared__ uint32_t smu[];
    uint32_t sb = s2u(smu);
    int tid = threadIdx.x, warp = tid >> 5, lane = tid & 31;
    int wm = warp & 1, wn = warp >> 1;
    int r = lane >> 2, c = lane & 3;
    int row0 = blockIdx.y * 128, col0 = blockIdx.x * 128;
    int KPu = Kd >> 1;
    int nchk = Kd / 32;

    int la  = lane & 15;
    int lga = (lane >> 4) * 4;
    int lb  = (lane & 7) + ((lane >> 4) << 3);
    int lcb = ((lane >> 3) & 1) * 4;

    float acc[4][4][4];
    #pragma unroll
    for (int mt = 0; mt < 4; mt++)
        #pragma unroll
        for (int nt = 0; nt < 4; nt++)
            #pragma unroll
            for (int i = 0; i < 4; i++) acc[mt][nt][i] = 0.f;

    auto stage_load = [&](int s, int kcu) {
        uint32_t stb = sb + s * STG_B;
        #pragma unroll
        for (int i = 0; i < 2; i++) {
            int cid = i * 256 + tid;
            int row = cid >> 2, kj = cid & 3;
            const uint32_t* sh = Ah + (size_t)(row0 + row) * KPu + kcu + kj * 4;
            uint32_t dst = stb + (row * GST + kj * 4) * 4;
            int sz = (row0 + row < M) ? 16 : 0;
            CP16(dst, sh, sz);
        }
        #pragma unroll
        for (int i = 0; i < 2; i++) {
            int cid = i * 256 + tid;
            int row = cid >> 2, kj = cid & 3;
            const uint32_t* sh = Wh + (size_t)(col0 + row) * KPu + kcu + kj * 4;
            uint32_t dst = stb + (AB_U32 + row * GST + kj * 4) * 4;
            CP16(dst, sh, 16);
        }
        CP_COMMIT();
    };

    stage_load(0, 0);
    stage_load(1, 16);

    for (int ch = 0; ch < nchk; ch++) {
        if (ch + 2 < nchk) { stage_load((ch + 2) % 3, (ch + 2) * 16); CP_WAIT2(); }
        else if (ch + 1 < nchk) { CP_WAIT1(); }
        else { CP_WAIT0(); }
        __syncthreads();

        uint32_t apb = sb + (ch % 3) * STG_B;
        uint32_t bpb = apb + AB_U32 * 4;

        #pragma unroll
        for (int kk = 0; kk < 2; kk++) {
            int kb = kk * 8;
            uint32_t fah[4][4];
            #pragma unroll
            for (int mt = 0; mt < 4; mt++)
                ldsm4(fah[mt], apb + (((wm*64 + mt*16 + la) * GST) + kb + lga) * 4);
            uint32_t fb[2][4];
            #pragma unroll
            for (int p = 0; p < 2; p++)
                ldsm4(fb[p], bpb + (((wn*32 + p*16 + lb) * GST) + kb + lcb) * 4);
            #pragma unroll
            for (int nt = 0; nt < 4; nt++) {
                uint32_t b0 = fb[nt >> 1][(nt & 1) * 2];
                uint32_t b1 = fb[nt >> 1][(nt & 1) * 2 + 1];
                #pragma unroll
                for (int mt = 0; mt < 4; mt++) mma16h(acc[mt][nt], fah[mt], b0, b1);
            }
        }
        __syncthreads();
    }

    if (C16) {
        int Nh = Nn >> 1;
        #pragma unroll
        for (int mt = 0; mt < 4; mt++) {
            int rowa = row0 + wm * 64 + mt * 16 + r;
            #pragma unroll
            for (int nt = 0; nt < 4; nt++) {
                int cp = (col0 >> 1) + wn * 16 + nt * 4 + c;
                if (rowa < M)
                    C16[(size_t)rowa * Nh + cp] = h2u(acc[mt][nt][0], acc[mt][nt][1]);
                if (rowa + 8 < M)
                    C16[(size_t)(rowa + 8) * Nh + cp] = h2u(acc[mt][nt][2], acc[mt][nt][3]);
            }
        }
    } else {
        #pragma unroll
        for (int mt = 0; mt < 4; mt++) {
            int rowa = row0 + wm * 64 + mt * 16 + r;
            #pragma unroll
            for (int nt = 0; nt < 4; nt++) {
                int colb = col0 + wn * 32 + nt * 8 + 2 * c;
                float bv0 = bias ? bias[colb]     : 0.f;
                float bv1 = bias ? bias[colb + 1] : 0.f;
                if (rowa < M) {
                    float2 v = make_float2(acc[mt][nt][0] + bv0, acc[mt][nt][1] + bv1);
                    *(float2*)&C[(size_t)rowa * Nn + colb] = v;
                }
                if (rowa + 8 < M) {
                    float2 v = make_float2(acc[mt][nt][2] + bv0, acc[mt][nt][3] + bv1);
                    *(float2*)&C[(size_t)(rowa + 8) * Nn + colb] = v;
                }
            }
        }
    }
}

// ---------------------------------------------------------------------------
// fp16 tensor-core attention (R13 structure: 9-tile loop); fp16 bias table.
// ---------------------------------------------------------------------------
#define SPQ 36
#define SPV 140

__global__ void __launch_bounds__(256)
attn_mma(const uint32_t* __restrict__ Q16, const uint32_t* __restrict__ KV16,
         const __half* __restrict__ bias16, uint32_t* __restrict__ Oh) {
    extern __shared__ uint32_t sm4[];
    uint32_t* Kh = sm4;                  // [272][36]
    uint32_t* Vh = Kh + 272 * SPQ;       // [64][140]
    uint32_t* Qh = Vh + 64 * SPV;        // [128][36]
    __half* Vhb = (__half*)Vh;

    int bh = blockIdx.x;
    int b = bh / Hh, h = bh - b * Hh;
    int tid = threadIdx.x, wr = tid >> 5, lane = tid & 31;
    int r = lane >> 2, c = lane & 3;

    int la  = lane & 15;
    int lga = (lane >> 4) * 4;
    int lb  = (lane & 7) + ((lane >> 4) << 3);
    int lcb = ((lane >> 3) & 1) * 4;

    uint32_t kba = s2u(Kh), vba = s2u(Vh), qba = s2u(Qh);

    const uint32_t* kvb = KV16 + (size_t)b * Kc * Dk + h * 32;
    for (int i = tid; i < 272 * 32; i += 256) {
        int kpos = i >> 5, dp = i & 31;
        uint32_t uk = 0u, uv = 0u;
        if (kpos < Kc) {
            const uint32_t* p = kvb + (size_t)kpos * Dk;
            uk = p[dp];
            uv = p[384 + dp];
        }
        Kh[kpos * SPQ + dp] = uk;
        __half2 hv = *reinterpret_cast<__half2*>(&uv);
        Vhb[(2*dp)   * 280 + kpos] = __low2half(hv);
        Vhb[(2*dp+1) * 280 + kpos] = __high2half(hv);
    }

    #pragma unroll 1
    for (int bx = 0; bx < 9; bx++) {
        int n0 = bx * 128;
        __syncthreads();
        for (int i = tid; i < 128 * 32; i += 256) {
            int rl = i >> 5, dp = i & 31;
            int n = n0 + rl; if (n > 1024) n = 1024;
            Qh[rl * SPQ + dp] = Q16[((size_t)b * Nk + n) * 384 + h * 32 + dp];
        }
        __syncthreads();

        int m0 = wr * 16;
        uint32_t qfh[4][4];
        #pragma unroll
        for (int kt = 0; kt < 4; kt++)
            ldsm4(qfh[kt], qba + ((m0 + la) * SPQ + kt*8 + lga) * 4);

        float lg[33][4];
        #pragma unroll
        for (int nt = 0; nt < 33; nt++)
            #pragma unroll
            for (int i = 0; i < 4; i++) lg[nt][i] = 0.f;

        #pragma unroll
        for (int gq = 0; gq < 8; gq++) {
            #pragma unroll
            for (int kt = 0; kt < 4; kt++) {
                uint32_t kf[2][4];
                #pragma unroll
                for (int p = 0; p < 2; p++)
                    ldsm4(kf[p], kba + (((gq*4 + p*2)*8 + lb) * SPQ + kt*8 + lcb) * 4);
                #pragma unroll
                for (int x = 0; x < 4; x++) {
                    uint32_t b0 = kf[x >> 1][(x & 1) * 2];
                    uint32_t b1 = kf[x >> 1][(x & 1) * 2 + 1];
                    mma16h(lg[gq*4 + x], qfh[kt], b0, b1);
                }
            }
        }
        #pragma unroll
        for (int kt = 0; kt < 4; kt++) {
            int kr = (32*8 + r) * SPQ + kt*8 + c;
            mma16h(lg[32], qfh[kt], Kh[kr], Kh[kr + 4]);
        }

        int nr  = n0 + m0 + r;
        int nr8 = nr + 8;
        const __half* bp0 = bias16 + ((size_t)h * Nk + (nr  > 1024 ? 1024 : nr )) * KB2;
        const __half* bp1 = bias16 + ((size_t)h * Nk + (nr8 > 1024 ? 1024 : nr8)) * KB2;
        #pragma unroll
        for (int nt = 0; nt < 33; nt++) {
            int k0 = nt*8 + 2*c, k1 = k0 + 1;
            uint32_t u0 = *(const uint32_t*)(bp0 + k0);
            uint32_t u1 = *(const uint32_t*)(bp1 + k0);
            float2 f0 = __half22float2(*reinterpret_cast<__half2*>(&u0));
            float2 f1 = __half22float2(*reinterpret_cast<__half2*>(&u1));
            lg[nt][0] = (k0 < Kc) ? lg[nt][0] * 0.125f + f0.x : -1e30f;
            lg[nt][1] = (k1 < Kc) ? lg[nt][1] * 0.125f + f0.y : -1e30f;
            lg[nt][2] = (k0 < Kc) ? lg[nt][2] * 0.125f + f1.x : -1e30f;
            lg[nt][3] = (k1 < Kc) ? lg[nt][3] * 0.125f + f1.y : -1e30f;
        }

        float mx0 = -1e30f, mx1 = -1e30f;
        #pragma unroll
        for (int nt = 0; nt < 33; nt++) {
            mx0 = fmaxf(mx0, fmaxf(lg[nt][0], lg[nt][1]));
            mx1 = fmaxf(mx1, fmaxf(lg[nt][2], lg[nt][3]));
        }
        mx0 = fmaxf(mx0, __shfl_xor_sync(0xffffffffu, mx0, 1));
        mx0 = fmaxf(mx0, __shfl_xor_sync(0xffffffffu, mx0, 2));
        mx1 = fmaxf(mx1, __shfl_xor_sync(0xffffffffu, mx1, 1));
        mx1 = fmaxf(mx1, __shfl_xor_sync(0xffffffffu, mx1, 2));
        float s0 = 0.f, s1 = 0.f;
        #pragma unroll
        for (int nt = 0; nt < 33; nt++) {
            lg[nt][0] = __expf(lg[nt][0] - mx0); s0 += lg[nt][0];
            lg[nt][1] = __expf(lg[nt][1] - mx0); s0 += lg[nt][1];
            lg[nt][2] = __expf(lg[nt][2] - mx1); s1 += lg[nt][2];
            lg[nt][3] = __expf(lg[nt][3] - mx1); s1 += lg[nt][3];
        }
        s0 += __shfl_xor_sync(0xffffffffu, s0, 1);
        s0 += __shfl_xor_sync(0xffffffffu, s0, 2);
        s1 += __shfl_xor_sync(0xffffffffu, s1, 1);
        s1 += __shfl_xor_sync(0xffffffffu, s1, 2);
        float inv0 = 1.f / s0, inv1 = 1.f / s1;

        float oacc[8][4];
        #pragma unroll
        for (int nt = 0; nt < 8; nt++)
            #pragma unroll
            for (int i = 0; i < 4; i++) oacc[nt][i] = 0.f;

        #pragma unroll
        for (int kt2 = 0; kt2 < 17; kt2++) {
            uint32_t ph[4];
            int e0 = 2*kt2, e1 = 2*kt2 + 1;
            ph[0] = h2u(lg[e0][0], lg[e0][1]);
            ph[1] = h2u(lg[e0][2], lg[e0][3]);
            if (e1 < 33) {
                ph[2] = h2u(lg[e1][0], lg[e1][1]);
                ph[3] = h2u(lg[e1][2], lg[e1][3]);
            } else {
                ph[2] = ph[3] = 0u;
            }
            uint32_t vf[4][4];
            #pragma unroll
            for (int p = 0; p < 4; p++)
                ldsm4(vf[p], vba + ((p*16 + lb) * SPV + kt2*8 + lcb) * 4);
            #pragma unroll
            for (int nt = 0; nt < 8; nt++) {
                uint32_t b0 = vf[nt >> 1][(nt & 1) * 2];
                uint32_t b1 = vf[nt >> 1][(nt & 1) * 2 + 1];
                mma16h(oacc[nt], ph, b0, b1);
            }
        }

        bool v0 = (nr <= 1024), v1 = (nr8 <= 1024);
        size_t ro0 = ((size_t)b * Nk + nr ) * (Dk/2) + h * (dh/2);
        size_t ro1 = ((size_t)b * Nk + nr8) * (Dk/2) + h * (dh/2);
        #pragma unroll
        for (int nt = 0; nt < 8; nt++) {
            if (v0) Oh[ro0 + nt*4 + c] = h2u(oacc[nt][0] * inv0, oacc[nt][1] * inv0);
            if (v1) Oh[ro1 + nt*4 + c] = h2u(oacc[nt][2] * inv1, oacc[nt][3] * inv1);
        }
    }
}

// ---------------------------------------------------------------------------
// Launch
// ---------------------------------------------------------------------------
extern "C" void kernel_launch(void* const* d_in, const int* in_sizes, int n_in,
                              void* d_out, int out_size) {
    const float* x       = (const float*)d_in[0];
    const float* W_logit = (const float*)d_in[1];
    const float* Wq      = (const float*)d_in[2];
    const float* Wkv     = (const float*)d_in[3];
    const float* Wo      = (const float*)d_in[4];
    const float* bo      = (const float*)d_in[5];
    const float* cw1     = (const float*)d_in[6];
    const float* cb1     = (const float*)d_in[7];
    const float* cw2     = (const float*)d_in[8];
    const float* cb2     = (const float*)d_in[9];
    const float* feats   = (const float*)d_in[10];
    const float* maskp   = (const float*)d_in[11];
    float* out = (float*)d_out;

    __half* bias16;
    uint32_t *xh, *ch, *q16, *kv16, *oh, *wqh, *wkvh, *woh;
    cudaGetSymbolAddress((void**)&bias16, g_bias16);
    cudaGetSymbolAddress((void**)&xh,   g_xh);
    cudaGetSymbolAddress((void**)&ch,   g_ch);
    cudaGetSymbolAddress((void**)&q16,  g_q16);
    cudaGetSymbolAddress((void**)&kv16, g_kv16);
    cudaGetSymbolAddress((void**)&oh,   g_oh);
    cudaGetSymbolAddress((void**)&wqh,  g_wqh);
    cudaGetSymbolAddress((void**)&wkvh, g_wkvh);
    cudaGetSymbolAddress((void**)&woh,  g_woh);

    const int GEMM_SMEM = 3 * STG_B;   // 61440
    cudaFuncSetAttribute(gemm_cp, cudaFuncAttributeMaxDynamicSharedMemorySize, GEMM_SMEM);

    int n4q  = Dk * Dk / 8;
    int n4kv = 2 * Dk * Dk / 8;
    int n4x  = MQ * Dk / 8;

    cvt_kernel<<<(n4x + 255)/256, 256>>>((const float4*)x, (uint4*)xh, n4x);
    cvt_kernel<<<(n4q + 255)/256, 256>>>((const float4*)Wq, (uint4*)wqh, n4q);
    pool_kernel<<<dim3(Tt + 1, Bk), 256>>>(x, W_logit, ch);
    // Q = x @ Wq^T  -> fp16 packed
    gemm_cp<<<dim3(Dk/128, (MQ + 127)/128), 256, GEMM_SMEM>>>(xh, wqh, nullptr, nullptr, q16, MQ, Dk, Dk);
    cvt_kernel<<<(n4kv + 255)/256, 256>>>((const float4*)Wkv, (uint4*)wkvh, n4kv);
    cvt_kernel<<<(n4q + 255)/256, 256>>>((const float4*)Wo, (uint4*)woh, n4q);
    cpb_kernel<<<(NKp + 255) / 256, 256>>>(feats, maskp, cw1, cb1, cw2, cb2, bias16);
    // KV = ctx @ Wkv^T -> fp16 packed
    gemm_cp<<<dim3((2*Dk)/128, (MKV + 127)/128), 256, GEMM_SMEM>>>(ch, wkvh, nullptr, nullptr, kv16, MKV, 2*Dk, Dk);

    const size_t ATTN_SMEM = (size_t)(272*SPQ + 64*SPV + 128*SPQ) * sizeof(uint32_t); // 93440
    cudaFuncSetAttribute(attn_mma, cudaFuncAttributeMaxDynamicSharedMemorySize, (int)ATTN_SMEM);
    attn_mma<<<Bk * Hh, 256, ATTN_SMEM>>>(q16, kv16, bias16, oh);

    // out = O @ Wo^T + bo  (fp32)
    gemm_cp<<<dim3(Dk/128, (MQ + 127)/128), 256, GEMM_SMEM>>>(oh, woh, bo, out, nullptr, MQ, Dk, Dk);
}

// round 17
// speedup vs baseline: 1.4713x; 1.1015x over previous
#include <cuda_runtime.h>
#include <cuda_fp16.h>
#include <cstdint>

// Problem constants
#define Bk   32
#define Nk   1025
#define Dk   768
#define Hh   12
#define dh   64
#define Tt   256
#define Kc   257
#define NKp  (Nk*Kc)
#define MQ   (Bk*Nk)      // 32800
#define MKV  (Bk*Kc)      // 8224
#define KB2  264          // padded bias row (halves)

// Scratch (device globals)
__device__ __half   g_bias16[(size_t)Hh*Nk*KB2];
__device__ uint32_t g_xh  [MQ*Dk/2];
__device__ uint32_t g_ch  [MKV*Dk/2];
__device__ uint32_t g_q16 [MQ*Dk/2];
__device__ uint32_t g_kv16[MKV*Dk];
__device__ uint32_t g_oh  [MQ*Dk/2];
__device__ uint32_t g_wqh [Dk*Dk/2];
__device__ uint32_t g_wkvh[Dk*Dk];
__device__ uint32_t g_woh [Dk*Dk/2];

// ---------------------------------------------------------------------------
// helpers
// ---------------------------------------------------------------------------
__device__ __forceinline__ uint32_t h2u(float f0, float f1) {
    __half2 h = __floats2half2_rn(f0, f1);
    return *reinterpret_cast<uint32_t*>(&h);
}
__device__ __forceinline__ void mma16h(float* d, const uint32_t* a, uint32_t b0, uint32_t b1) {
    asm volatile(
        "mma.sync.aligned.m16n8k16.row.col.f32.f16.f16.f32 "
        "{%0,%1,%2,%3}, {%4,%5,%6,%7}, {%8,%9}, {%0,%1,%2,%3};"
        : "+f"(d[0]), "+f"(d[1]), "+f"(d[2]), "+f"(d[3])
        : "r"(a[0]), "r"(a[1]), "r"(a[2]), "r"(a[3]), "r"(b0), "r"(b1));
}
__device__ __forceinline__ void ldsm4(uint32_t* d, uint32_t addr) {
    asm volatile("ldmatrix.sync.aligned.m8n8.x4.shared.b16 {%0,%1,%2,%3}, [%4];"
        : "=r"(d[0]), "=r"(d[1]), "=r"(d[2]), "=r"(d[3]) : "r"(addr));
}
__device__ __forceinline__ uint32_t s2u(const void* p) {
    uint32_t a;
    asm("{ .reg .u64 t; cvta.to.shared.u64 t, %1; cvt.u32.u64 %0, t; }" : "=r"(a) : "l"(p));
    return a;
}
#define CP16(dst, src, sz) \
    asm volatile("cp.async.cg.shared.global [%0], [%1], 16, %2;" \
                 :: "r"(dst), "l"(src), "r"(sz) : "memory")
#define CP_COMMIT() asm volatile("cp.async.commit_group;" ::: "memory")
#define CP_WAIT2()  asm volatile("cp.async.wait_group 2;" ::: "memory")
#define CP_WAIT1()  asm volatile("cp.async.wait_group 1;" ::: "memory")
#define CP_WAIT0()  asm volatile("cp.async.wait_group 0;" ::: "memory")

// ---------------------------------------------------------------------------
// convert fp32 -> packed fp16
// ---------------------------------------------------------------------------
__global__ void cvt_kernel(const float4* __restrict__ in, uint4* __restrict__ out, int n4) {
    int i = blockIdx.x * 256 + threadIdx.x;
    if (i >= n4) return;
    float4 a = in[2*i], b = in[2*i + 1];
    uint4 H;
    H.x = h2u(a.x, a.y);
    H.y = h2u(a.z, a.w);
    H.z = h2u(b.x, b.y);
    H.w = h2u(b.z, b.w);
    out[i] = H;
}

// ---------------------------------------------------------------------------
// Pooling — writes packed fp16 ctx
// ---------------------------------------------------------------------------
__global__ void pool_kernel(const float* __restrict__ x,
                            const float* __restrict__ wl,
                            uint32_t* __restrict__ ctx16) {
    int t = blockIdx.x;
    int b = blockIdx.y;
    int tid = threadIdx.x;
    const float* xb = x + (size_t)b * Nk * Dk;
    if (t == Tt) {
        uint32_t* dst = ctx16 + (size_t)b * Kc * (Dk/2);
        for (int dp = tid; dp < Dk/2; dp += 256)
            dst[dp] = h2u(xb[2*dp], xb[2*dp + 1]);
        return;
    }
    int gy = t >> 4, gx = t & 15;
    int n0 = 1 + (gy * 2) * 32 + gx * 2;
    int rows[4] = { n0, n0 + 1, n0 + 32, n0 + 33 };

    float p[4] = {0.f, 0.f, 0.f, 0.f};
    for (int dd = tid; dd < Dk; dd += 256) {
        float wv = wl[dd];
        p[0] += xb[(size_t)rows[0]*Dk + dd] * wv;
        p[1] += xb[(size_t)rows[1]*Dk + dd] * wv;
        p[2] += xb[(size_t)rows[2]*Dk + dd] * wv;
        p[3] += xb[(size_t)rows[3]*Dk + dd] * wv;
    }
    __shared__ float wred[4][8];
    __shared__ float sw4[4];
    int lane = tid & 31, w = tid >> 5;
    #pragma unroll
    for (int i = 0; i < 4; i++) {
        float v = p[i];
        #pragma unroll
        for (int off = 16; off; off >>= 1) v += __shfl_xor_sync(0xffffffffu, v, off);
        if (lane == 0) wred[i][w] = v;
    }
    __syncthreads();
    if (tid == 0) {
        float s[4];
        #pragma unroll
        for (int i = 0; i < 4; i++) {
            float a = 0.f;
            for (int ww = 0; ww < 8; ww++) a += wred[i][ww];
            s[i] = a;
        }
        float m = fmaxf(fmaxf(s[0], s[1]), fmaxf(s[2], s[3]));
        float e[4], su = 0.f;
        #pragma unroll
        for (int i = 0; i < 4; i++) { e[i] = expf(s[i] - m); su += e[i]; }
        float inv = 1.f / su;
        #pragma unroll
        for (int i = 0; i < 4; i++) sw4[i] = e[i] * inv;
    }
    __syncthreads();
    float w0 = sw4[0], w1 = sw4[1], w2 = sw4[2], w3 = sw4[3];
    uint32_t* dst = ctx16 + ((size_t)b * Kc + 1 + t) * (Dk/2);
    const float* r0 = xb + (size_t)rows[0]*Dk;
    const float* r1 = xb + (size_t)rows[1]*Dk;
    const float* r2 = xb + (size_t)rows[2]*Dk;
    const float* r3 = xb + (size_t)rows[3]*Dk;
    for (int dp = tid; dp < Dk/2; dp += 256) {
        int d0 = 2*dp, d1 = d0 + 1;
        float v0 = w0*r0[d0] + w1*r1[d0] + w2*r2[d0] + w3*r3[d0];
        float v1 = w0*r0[d1] + w1*r1[d1] + w2*r2[d1] + w3*r3[d1];
        dst[dp] = h2u(v0, v1);
    }
}

// ---------------------------------------------------------------------------
// CPB bias — fp16 padded [H][N][KB2]
// ---------------------------------------------------------------------------
__global__ void cpb_kernel(const float* __restrict__ feats, const float* __restrict__ mask,
                           const float* __restrict__ w1, const float* __restrict__ b1,
                           const float* __restrict__ w2, const float* __restrict__ b2,
                           __half* __restrict__ bias16) {
    __shared__ float sw1[64], sb1[32], sw2[12*32], sb2[12];
    int tid = threadIdx.x;
    if (tid < 64) sw1[tid] = w1[tid];
    if (tid >= 64 && tid < 96) sb1[tid - 64] = b1[tid - 64];
    if (tid >= 96 && tid < 108) sb2[tid - 96] = b2[tid - 96];
    for (int i = tid; i < 384; i += 256) sw2[i] = w2[i];
    __syncthreads();
    int idx = blockIdx.x * 256 + tid;
    if (idx >= NKp) return;
    int n = idx / Kc, k = idx - n * Kc;
    float f0 = feats[2*idx], f1 = feats[2*idx + 1];
    float m = mask[idx];
    float acc[12];
    #pragma unroll
    for (int h = 0; h < 12; h++) acc[h] = sb2[h];
    #pragma unroll
    for (int j = 0; j < 32; j++) {
        float tt = f0 * sw1[2*j] + f1 * sw1[2*j + 1] + sb1[j];
        float g = 0.5f * tt * (1.0f + erff(tt * 0.7071067811865475f));
        #pragma unroll
        for (int h = 0; h < 12; h++) acc[h] += sw2[h*32 + j] * g;
    }
    size_t base = (size_t)n * KB2 + k;
    #pragma unroll
    for (int h = 0; h < 12; h++)
        bias16[(size_t)h * (Nk * KB2) + base] = __float2half(acc[h] * m);
}

// ---------------------------------------------------------------------------
// cp.async 3-stage fp16 GEMM, 2 CTAs/SM, ldmatrix fragments. (R16 config)
// ---------------------------------------------------------------------------
#define GST   20
#define AB_U32 (128*GST)
#define BB_U32 (128*GST)
#define STG_U32 (AB_U32 + BB_U32)
#define STG_B  (STG_U32*4)

__global__ void __launch_bounds__(256, 2)
gemm_cp(const uint32_t* __restrict__ Ah, const uint32_t* __restrict__ Wh,
        const float* __restrict__ bias, float* __restrict__ C,
        uint32_t* __restrict__ C16,
        int M, int Nn, int Kd) {
    extern __shared__ uint32_t smu[];
    uint32_t sb = s2u(smu);
    int tid = threadIdx.x, warp = tid >> 5, lane = tid & 31;
    int wm = warp & 1, wn = warp >> 1;
    int r = lane >> 2, c = lane & 3;
    int row0 = blockIdx.y * 128, col0 = blockIdx.x * 128;
    int KPu = Kd >> 1;
    int nchk = Kd / 32;

    int la  = lane & 15;
    int lga = (lane >> 4) * 4;
    int lb  = (lane & 7) + ((lane >> 4) << 3);
    int lcb = ((lane >> 3) & 1) * 4;

    float acc[4][4][4];
    #pragma unroll
    for (int mt = 0; mt < 4; mt++)
        #pragma unroll
        for (int nt = 0; nt < 4; nt++)
            #pragma unroll
            for (int i = 0; i < 4; i++) acc[mt][nt][i] = 0.f;

    auto stage_load = [&](int s, int kcu) {
        uint32_t stb = sb + s * STG_B;
        #pragma unroll
        for (int i = 0; i < 2; i++) {
            int cid = i * 256 + tid;
            int row = cid >> 2, kj = cid & 3;
            const uint32_t* sh = Ah + (size_t)(row0 + row) * KPu + kcu + kj * 4;
            uint32_t dst = stb + (row * GST + kj * 4) * 4;
            int sz = (row0 + row < M) ? 16 : 0;
            CP16(dst, sh, sz);
        }
        #pragma unroll
        for (int i = 0; i < 2; i++) {
            int cid = i * 256 + tid;
            int row = cid >> 2, kj = cid & 3;
            const uint32_t* sh = Wh + (size_t)(col0 + row) * KPu + kcu + kj * 4;
            uint32_t dst = stb + (AB_U32 + row * GST + kj * 4) * 4;
            CP16(dst, sh, 16);
        }
        CP_COMMIT();
    };

    stage_load(0, 0);
    stage_load(1, 16);

    for (int ch = 0; ch < nchk; ch++) {
        if (ch + 2 < nchk) { stage_load((ch + 2) % 3, (ch + 2) * 16); CP_WAIT2(); }
        else if (ch + 1 < nchk) { CP_WAIT1(); }
        else { CP_WAIT0(); }
        __syncthreads();

        uint32_t apb = sb + (ch % 3) * STG_B;
        uint32_t bpb = apb + AB_U32 * 4;

        #pragma unroll
        for (int kk = 0; kk < 2; kk++) {
            int kb = kk * 8;
            uint32_t fah[4][4];
            #pragma unroll
            for (int mt = 0; mt < 4; mt++)
                ldsm4(fah[mt], apb + (((wm*64 + mt*16 + la) * GST) + kb + lga) * 4);
            uint32_t fb[2][4];
            #pragma unroll
            for (int p = 0; p < 2; p++)
                ldsm4(fb[p], bpb + (((wn*32 + p*16 + lb) * GST) + kb + lcb) * 4);
            #pragma unroll
            for (int nt = 0; nt < 4; nt++) {
                uint32_t b0 = fb[nt >> 1][(nt & 1) * 2];
                uint32_t b1 = fb[nt >> 1][(nt & 1) * 2 + 1];
                #pragma unroll
                for (int mt = 0; mt < 4; mt++) mma16h(acc[mt][nt], fah[mt], b0, b1);
            }
        }
        __syncthreads();
    }

    if (C16) {
        int Nh = Nn >> 1;
        #pragma unroll
        for (int mt = 0; mt < 4; mt++) {
            int rowa = row0 + wm * 64 + mt * 16 + r;
            #pragma unroll
            for (int nt = 0; nt < 4; nt++) {
                int cp = (col0 >> 1) + wn * 16 + nt * 4 + c;
                if (rowa < M)
                    C16[(size_t)rowa * Nh + cp] = h2u(acc[mt][nt][0], acc[mt][nt][1]);
                if (rowa + 8 < M)
                    C16[(size_t)(rowa + 8) * Nh + cp] = h2u(acc[mt][nt][2], acc[mt][nt][3]);
            }
        }
    } else {
        #pragma unroll
        for (int mt = 0; mt < 4; mt++) {
            int rowa = row0 + wm * 64 + mt * 16 + r;
            #pragma unroll
            for (int nt = 0; nt < 4; nt++) {
                int colb = col0 + wn * 32 + nt * 8 + 2 * c;
                float bv0 = bias ? bias[colb]     : 0.f;
                float bv1 = bias ? bias[colb + 1] : 0.f;
                if (rowa < M) {
                    float2 v = make_float2(acc[mt][nt][0] + bv0, acc[mt][nt][1] + bv1);
                    *(float2*)&C[(size_t)rowa * Nn + colb] = v;
                }
                if (rowa + 8 < M) {
                    float2 v = make_float2(acc[mt][nt][2] + bv0, acc[mt][nt][3] + bv1);
                    *(float2*)&C[(size_t)(rowa + 8) * Nn + colb] = v;
                }
            }
        }
    }
}

// ---------------------------------------------------------------------------
// fp16 tensor-core attention; Q double-buffered via cp.async so the per-tile
// Q fill overlaps the previous tile's full compute.
// ---------------------------------------------------------------------------
#define SPQ 36
#define SPV 140
#define QBUF_U32 (128*SPQ)

__global__ void __launch_bounds__(256)
attn_mma(const uint32_t* __restrict__ Q16, const uint32_t* __restrict__ KV16,
         const __half* __restrict__ bias16, uint32_t* __restrict__ Oh) {
    extern __shared__ uint32_t sm4[];
    uint32_t* Kh = sm4;                  // [272][36]
    uint32_t* Vh = Kh + 272 * SPQ;       // [64][140]
    uint32_t* Qh = Vh + 64 * SPV;        // [2][128][36]
    __half* Vhb = (__half*)Vh;

    int bh = blockIdx.x;
    int b = bh / Hh, h = bh - b * Hh;
    int tid = threadIdx.x, wr = tid >> 5, lane = tid & 31;
    int r = lane >> 2, c = lane & 3;

    int la  = lane & 15;
    int lga = (lane >> 4) * 4;
    int lb  = (lane & 7) + ((lane >> 4) << 3);
    int lcb = ((lane >> 3) & 1) * 4;

    uint32_t kba = s2u(Kh), vba = s2u(Vh), qba = s2u(Qh);

    // prefetch Q tile for iteration bx into buffer bx&1 (4 x 16B per thread)
    auto q_prefetch = [&](int bx) {
        if (bx >= 9) return;
        int n0 = bx * 128;
        uint32_t dstb = qba + (bx & 1) * QBUF_U32 * 4;
        #pragma unroll
        for (int i = 0; i < 4; i++) {
            int cid = i * 256 + tid;          // 0..1023
            int row = cid >> 3, part = cid & 7;
            int n = n0 + row; if (n > 1024) n = 1024;
            const uint32_t* src = Q16 + ((size_t)b * Nk + n) * 384 + h * 32 + part * 4;
            CP16(dstb + (row * SPQ + part * 4) * 4, src, 16);
        }
        CP_COMMIT();
    };

    q_prefetch(0);

    // K/V fill (regular loads; overlaps with the Q prefetch naturally)
    const uint32_t* kvb = KV16 + (size_t)b * Kc * Dk + h * 32;
    for (int i = tid; i < 272 * 32; i += 256) {
        int kpos = i >> 5, dp = i & 31;
        uint32_t uk = 0u, uv = 0u;
        if (kpos < Kc) {
            const uint32_t* p = kvb + (size_t)kpos * Dk;
            uk = p[dp];
            uv = p[384 + dp];
        }
        Kh[kpos * SPQ + dp] = uk;
        __half2 hv = *reinterpret_cast<__half2*>(&uv);
        Vhb[(2*dp)   * 280 + kpos] = __low2half(hv);
        Vhb[(2*dp+1) * 280 + kpos] = __high2half(hv);
    }

    #pragma unroll 1
    for (int bx = 0; bx < 9; bx++) {
        int n0 = bx * 128;
        CP_WAIT0();
        __syncthreads();   // Q buffer ready for all; K/V ready on first iter

        // extract Q fragments, then immediately prefetch next tile
        int m0 = wr * 16;
        uint32_t qb = qba + (bx & 1) * QBUF_U32 * 4;
        uint32_t qfh[4][4];
        #pragma unroll
        for (int kt = 0; kt < 4; kt++)
            ldsm4(qfh[kt], qb + ((m0 + la) * SPQ + kt*8 + lga) * 4);
        __syncthreads();   // all warps done reading this buffer's... (frags in regs; safe to refill other buffer only — no wait needed; barrier guards K-phase reuse isn't required. Kept minimal: prefetch targets the *other* buffer.)
        q_prefetch(bx + 1);

        float lg[33][4];
        #pragma unroll
        for (int nt = 0; nt < 33; nt++)
            #pragma unroll
            for (int i = 0; i < 4; i++) lg[nt][i] = 0.f;

        #pragma unroll
        for (int gq = 0; gq < 8; gq++) {
            #pragma unroll
            for (int kt = 0; kt < 4; kt++) {
                uint32_t kf[2][4];
                #pragma unroll
                for (int p = 0; p < 2; p++)
                    ldsm4(kf[p], kba + (((gq*4 + p*2)*8 + lb) * SPQ + kt*8 + lcb) * 4);
                #pragma unroll
                for (int x = 0; x < 4; x++) {
                    uint32_t b0 = kf[x >> 1][(x & 1) * 2];
                    uint32_t b1 = kf[x >> 1][(x & 1) * 2 + 1];
                    mma16h(lg[gq*4 + x], qfh[kt], b0, b1);
                }
            }
        }
        #pragma unroll
        for (int kt = 0; kt < 4; kt++) {
            int kr = (32*8 + r) * SPQ + kt*8 + c;
            mma16h(lg[32], qfh[kt], Kh[kr], Kh[kr + 4]);
        }

        int nr  = n0 + m0 + r;
        int nr8 = nr + 8;
        const __half* bp0 = bias16 + ((size_t)h * Nk + (nr  > 1024 ? 1024 : nr )) * KB2;
        const __half* bp1 = bias16 + ((size_t)h * Nk + (nr8 > 1024 ? 1024 : nr8)) * KB2;
        #pragma unroll
        for (int nt = 0; nt < 33; nt++) {
            int k0 = nt*8 + 2*c, k1 = k0 + 1;
            uint32_t u0 = *(const uint32_t*)(bp0 + k0);
            uint32_t u1 = *(const uint32_t*)(bp1 + k0);
            float2 f0 = __half22float2(*reinterpret_cast<__half2*>(&u0));
            float2 f1 = __half22float2(*reinterpret_cast<__half2*>(&u1));
            lg[nt][0] = (k0 < Kc) ? lg[nt][0] * 0.125f + f0.x : -1e30f;
            lg[nt][1] = (k1 < Kc) ? lg[nt][1] * 0.125f + f0.y : -1e30f;
            lg[nt][2] = (k0 < Kc) ? lg[nt][2] * 0.125f + f1.x : -1e30f;
            lg[nt][3] = (k1 < Kc) ? lg[nt][3] * 0.125f + f1.y : -1e30f;
        }

        float mx0 = -1e30f, mx1 = -1e30f;
        #pragma unroll
        for (int nt = 0; nt < 33; nt++) {
            mx0 = fmaxf(mx0, fmaxf(lg[nt][0], lg[nt][1]));
            mx1 = fmaxf(mx1, fmaxf(lg[nt][2], lg[nt][3]));
        }
        mx0 = fmaxf(mx0, __shfl_xor_sync(0xffffffffu, mx0, 1));
        mx0 = fmaxf(mx0, __shfl_xor_sync(0xffffffffu, mx0, 2));
        mx1 = fmaxf(mx1, __shfl_xor_sync(0xffffffffu, mx1, 1));
        mx1 = fmaxf(mx1, __shfl_xor_sync(0xffffffffu, mx1, 2));
        float s0 = 0.f, s1 = 0.f;
        #pragma unroll
        for (int nt = 0; nt < 33; nt++) {
            lg[nt][0] = __expf(lg[nt][0] - mx0); s0 += lg[nt][0];
            lg[nt][1] = __expf(lg[nt][1] - mx0); s0 += lg[nt][1];
            lg[nt][2] = __expf(lg[nt][2] - mx1); s1 += lg[nt][2];
            lg[nt][3] = __expf(lg[nt][3] - mx1); s1 += lg[nt][3];
        }
        s0 += __shfl_xor_sync(0xffffffffu, s0, 1);
        s0 += __shfl_xor_sync(0xffffffffu, s0, 2);
        s1 += __shfl_xor_sync(0xffffffffu, s1, 1);
        s1 += __shfl_xor_sync(0xffffffffu, s1, 2);
        float inv0 = 1.f / s0, inv1 = 1.f / s1;

        float oacc[8][4];
        #pragma unroll
        for (int nt = 0; nt < 8; nt++)
            #pragma unroll
            for (int i = 0; i < 4; i++) oacc[nt][i] = 0.f;

        #pragma unroll
        for (int kt2 = 0; kt2 < 17; kt2++) {
            uint32_t ph[4];
            int e0 = 2*kt2, e1 = 2*kt2 + 1;
            ph[0] = h2u(lg[e0][0], lg[e0][1]);
            ph[1] = h2u(lg[e0][2], lg[e0][3]);
            if (e1 < 33) {
                ph[2] = h2u(lg[e1][0], lg[e1][1]);
                ph[3] = h2u(lg[e1][2], lg[e1][3]);
            } else {
                ph[2] = ph[3] = 0u;
            }
            uint32_t vf[4][4];
            #pragma unroll
            for (int p = 0; p < 4; p++)
                ldsm4(vf[p], vba + ((p*16 + lb) * SPV + kt2*8 + lcb) * 4);
            #pragma unroll
            for (int nt = 0; nt < 8; nt++) {
                uint32_t b0 = vf[nt >> 1][(nt & 1) * 2];
                uint32_t b1 = vf[nt >> 1][(nt & 1) * 2 + 1];
                mma16h(oacc[nt], ph, b0, b1);
            }
        }

        bool v0 = (nr <= 1024), v1 = (nr8 <= 1024);
        size_t ro0 = ((size_t)b * Nk + nr ) * (Dk/2) + h * (dh/2);
        size_t ro1 = ((size_t)b * Nk + nr8) * (Dk/2) + h * (dh/2);
        #pragma unroll
        for (int nt = 0; nt < 8; nt++) {
            if (v0) Oh[ro0 + nt*4 + c] = h2u(oacc[nt][0] * inv0, oacc[nt][1] * inv0);
            if (v1) Oh[ro1 + nt*4 + c] = h2u(oacc[nt][2] * inv1, oacc[nt][3] * inv1);
        }
    }
}

// ---------------------------------------------------------------------------
// Launch
// ---------------------------------------------------------------------------
extern "C" void kernel_launch(void* const* d_in, const int* in_sizes, int n_in,
                              void* d_out, int out_size) {
    const float* x       = (const float*)d_in[0];
    const float* W_logit = (const float*)d_in[1];
    const float* Wq      = (const float*)d_in[2];
    const float* Wkv     = (const float*)d_in[3];
    const float* Wo      = (const float*)d_in[4];
    const float* bo      = (const float*)d_in[5];
    const float* cw1     = (const float*)d_in[6];
    const float* cb1     = (const float*)d_in[7];
    const float* cw2     = (const float*)d_in[8];
    const float* cb2     = (const float*)d_in[9];
    const float* feats   = (const float*)d_in[10];
    const float* maskp   = (const float*)d_in[11];
    float* out = (float*)d_out;

    __half* bias16;
    uint32_t *xh, *ch, *q16, *kv16, *oh, *wqh, *wkvh, *woh;
    cudaGetSymbolAddress((void**)&bias16, g_bias16);
    cudaGetSymbolAddress((void**)&xh,   g_xh);
    cudaGetSymbolAddress((void**)&ch,   g_ch);
    cudaGetSymbolAddress((void**)&q16,  g_q16);
    cudaGetSymbolAddress((void**)&kv16, g_kv16);
    cudaGetSymbolAddress((void**)&oh,   g_oh);
    cudaGetSymbolAddress((void**)&wqh,  g_wqh);
    cudaGetSymbolAddress((void**)&wkvh, g_wkvh);
    cudaGetSymbolAddress((void**)&woh,  g_woh);

    const int GEMM_SMEM = 3 * STG_B;
    cudaFuncSetAttribute(gemm_cp, cudaFuncAttributeMaxDynamicSharedMemorySize, GEMM_SMEM);

    int n4q  = Dk * Dk / 8;
    int n4kv = 2 * Dk * Dk / 8;
    int n4x  = MQ * Dk / 8;

    cvt_kernel<<<(n4x + 255)/256, 256>>>((const float4*)x, (uint4*)xh, n4x);
    cvt_kernel<<<(n4q + 255)/256, 256>>>((const float4*)Wq, (uint4*)wqh, n4q);
    pool_kernel<<<dim3(Tt + 1, Bk), 256>>>(x, W_logit, ch);
    gemm_cp<<<dim3(Dk/128, (MQ + 127)/128), 256, GEMM_SMEM>>>(xh, wqh, nullptr, nullptr, q16, MQ, Dk, Dk);
    cvt_kernel<<<(n4kv + 255)/256, 256>>>((const float4*)Wkv, (uint4*)wkvh, n4kv);
    cvt_kernel<<<(n4q + 255)/256, 256>>>((const float4*)Wo, (uint4*)woh, n4q);
    cpb_kernel<<<(NKp + 255) / 256, 256>>>(feats, maskp, cw1, cb1, cw2, cb2, bias16);
    gemm_cp<<<dim3((2*Dk)/128, (MKV + 127)/128), 256, GEMM_SMEM>>>(ch, wkvh, nullptr, nullptr, kv16, MKV, 2*Dk, Dk);

    const size_t ATTN_SMEM = (size_t)(272*SPQ + 64*SPV + 2*QBUF_U32) * sizeof(uint32_t); // 111872
    cudaFuncSetAttribute(attn_mma, cudaFuncAttributeMaxDynamicSharedMemorySize, (int)ATTN_SMEM);
    attn_mma<<<Bk * Hh, 256, ATTN_SMEM>>>(q16, kv16, bias16, oh);

    gemm_cp<<<dim3(Dk/128, (MQ + 127)/128), 256, GEMM_SMEM>>>(oh, woh, bo, out, nullptr, MQ, Dk, Dk);
}